// round 2
// baseline (speedup 1.0000x reference)
#include <cuda_runtime.h>
#include <cuda_bf16.h>
#include <math.h>

// Problem constants (match reference generator)
#define NMAX 50000
#define EMAX 600000
#define HID  128
#define NG   64
#define ETMAX (EMAX + NMAX)

// ---------------- device scratch (static: allocation-free) ----------------
__device__ __align__(16) float    g_h[(size_t)NMAX * HID];     // layer input features
__device__ __align__(16) float    g_xp[(size_t)NMAX * HID];    // transformed features
__device__ __align__(16) float    g_out[(size_t)NMAX * HID];   // aggregation accumulator
__device__ float    g_als[NMAX];
__device__ float    g_ald[NMAX];
__device__ unsigned g_menc[NMAX];                // ordered-uint encoded max
__device__ float    g_den[NMAX];
__device__ float    g_alpha[ETMAX];
__device__ __align__(16) float    g_pool[NG * HID];
__device__ float    g_cnt[NG];

// monotonic float<->uint ordering encode (handles negatives)
__device__ __forceinline__ unsigned f_enc(float f) {
    unsigned u = __float_as_uint(f);
    return (u & 0x80000000u) ? ~u : (u | 0x80000000u);
}
__device__ __forceinline__ float f_dec(unsigned u) {
    return __uint_as_float((u & 0x80000000u) ? (u & 0x7FFFFFFFu) : ~u);
}

// ---------------- init kernels ----------------
__global__ void k_init_node(int n) {
    int i = blockIdx.x * blockDim.x + threadIdx.x;
    if (i >= n) return;
    g_menc[i] = f_enc(-INFINITY);
    g_den[i] = 0.0f;
}

__global__ void k_zero_out(int n32) {  // n32 = n*32 float4 slots
    int i = blockIdx.x * blockDim.x + threadIdx.x;
    if (i >= n32) return;
    ((float4*)g_out)[i] = make_float4(0.f, 0.f, 0.f, 0.f);
}

__global__ void k_pool_init() {
    int i = blockIdx.x * blockDim.x + threadIdx.x;
    if (i < NG * HID) g_pool[i] = 0.0f;
    if (i < NG) g_cnt[i] = 0.0f;
}

// ---------------- layer 1 transform: xp[n][j] = x[n] * W1[j] ----------------
__global__ void k_l1(const float* __restrict__ x, const float* __restrict__ W1, int n32) {
    int i = blockIdx.x * blockDim.x + threadIdx.x;
    if (i >= n32) return;
    float xv = x[i >> 5];
    float4 w = ((const float4*)W1)[i & 31];
    ((float4*)g_xp)[i] = make_float4(xv * w.x, xv * w.y, xv * w.z, xv * w.w);
}

// ---------------- GEMM: g_xp = g_h @ W  (n x 128 @ 128 x 128) ----------------
__global__ __launch_bounds__(256, 2) void k_gemm(const float* __restrict__ W, int n) {
    __shared__ float sA[16][128];   // [k][row]
    __shared__ float sB[16][128];   // [k][col]
    const int tid = threadIdx.x;
    const int row0 = blockIdx.x * 128;
    const int tx = tid & 15, ty = tid >> 4;
    float acc[8][8];
#pragma unroll
    for (int i = 0; i < 8; i++)
#pragma unroll
        for (int j = 0; j < 8; j++) acc[i][j] = 0.f;

    for (int k0 = 0; k0 < 128; k0 += 16) {
#pragma unroll
        for (int p = 0; p < 2; p++) {
            int r = (tid >> 2) + p * 64;
            int c = (tid & 3) * 4;
            float4 v = make_float4(0.f, 0.f, 0.f, 0.f);
            if (row0 + r < n)
                v = *(const float4*)&g_h[(size_t)(row0 + r) * 128 + k0 + c];
            sA[c + 0][r] = v.x; sA[c + 1][r] = v.y;
            sA[c + 2][r] = v.z; sA[c + 3][r] = v.w;
        }
#pragma unroll
        for (int p = 0; p < 2; p++) {
            int kk = (tid >> 5) + p * 8;
            int j = (tid & 31) * 4;
            *(float4*)&sB[kk][j] = *(const float4*)&W[(size_t)(k0 + kk) * 128 + j];
        }
        __syncthreads();
#pragma unroll
        for (int kk = 0; kk < 16; kk++) {
            float a[8], b[8];
            *(float4*)&a[0] = *(float4*)&sA[kk][ty * 8];
            *(float4*)&a[4] = *(float4*)&sA[kk][ty * 8 + 4];
            *(float4*)&b[0] = *(float4*)&sB[kk][tx * 8];
            *(float4*)&b[4] = *(float4*)&sB[kk][tx * 8 + 4];
#pragma unroll
            for (int i = 0; i < 8; i++)
#pragma unroll
                for (int j = 0; j < 8; j++) acc[i][j] += a[i] * b[j];
        }
        __syncthreads();
    }
#pragma unroll
    for (int i = 0; i < 8; i++) {
        int r = row0 + ty * 8 + i;
        if (r < n) {
            *(float4*)&g_xp[(size_t)r * 128 + tx * 8]     = *(float4*)&acc[i][0];
            *(float4*)&g_xp[(size_t)r * 128 + tx * 8 + 4] = *(float4*)&acc[i][4];
        }
    }
}

// ---------------- attention scalars: als/ald = xp . a_src / a_dst ----------------
__global__ void k_attn(const float* __restrict__ asv, const float* __restrict__ adv, int n) {
    int w = (blockIdx.x * blockDim.x + threadIdx.x) >> 5;
    int lane = threadIdx.x & 31;
    if (w >= n) return;
    float4 v = ((const float4*)g_xp)[(size_t)w * 32 + lane];
    float4 s4 = ((const float4*)asv)[lane];
    float4 d4 = ((const float4*)adv)[lane];
    float s = v.x * s4.x + v.y * s4.y + v.z * s4.z + v.w * s4.w;
    float d = v.x * d4.x + v.y * d4.y + v.z * d4.z + v.w * d4.w;
#pragma unroll
    for (int o = 16; o > 0; o >>= 1) {
        s += __shfl_down_sync(0xffffffffu, s, o);
        d += __shfl_down_sync(0xffffffffu, d, o);
    }
    if (lane == 0) { g_als[w] = s; g_ald[w] = d; }
}

// ---------------- edge pass A: alpha + segment max ----------------
__global__ void k_edge_max(const int* __restrict__ ei, int E, int ET) {
    int e = blockIdx.x * blockDim.x + threadIdx.x;
    if (e >= ET) return;
    int s, d;
    if (e < E) { s = ei[e]; d = ei[E + e]; }
    else       { s = d = e - E; }
    float a = g_als[s] + g_ald[d];
    a = (a > 0.f) ? a : 0.2f * a;
    g_alpha[e] = a;
    atomicMax(&g_menc[d], f_enc(a));
}

// ---------------- edge pass B: denominator ----------------
__global__ void k_edge_den(const int* __restrict__ ei, int E, int ET) {
    int e = blockIdx.x * blockDim.x + threadIdx.x;
    if (e >= ET) return;
    int d = (e < E) ? ei[E + e] : (e - E);
    float m = f_dec(g_menc[d]);
    atomicAdd(&g_den[d], __expf(g_alpha[e] - m));
}

// ---------------- edge pass C: weighted aggregation (warp per edge) ----------------
__global__ void k_edge_agg(const int* __restrict__ ei, int E, int ET) {
    int e = (blockIdx.x * blockDim.x + threadIdx.x) >> 5;
    int lane = threadIdx.x & 31;
    if (e >= ET) return;
    int s, d;
    if (e < E) { s = ei[e]; d = ei[E + e]; }
    else       { s = d = e - E; }
    float m = f_dec(g_menc[d]);
    float coef = __expf(g_alpha[e] - m) / g_den[d];
    float4 v = *(const float4*)&g_xp[(size_t)s * 128 + lane * 4];
    atomicAdd((float4*)&g_out[(size_t)d * 128 + lane * 4],
              make_float4(coef * v.x, coef * v.y, coef * v.z, coef * v.w));
}

// ---------------- bias + relu -> g_h ----------------
__global__ void k_bias_relu(const float* __restrict__ b, int n32) {
    int i = blockIdx.x * blockDim.x + threadIdx.x;
    if (i >= n32) return;
    float4 v = ((const float4*)g_out)[i];
    float4 bb = *(const float4*)&b[(i & 31) * 4];
    v.x = fmaxf(v.x + bb.x, 0.f);
    v.y = fmaxf(v.y + bb.y, 0.f);
    v.z = fmaxf(v.z + bb.z, 0.f);
    v.w = fmaxf(v.w + bb.w, 0.f);
    ((float4*)g_h)[i] = v;
}

// ---------------- mean-pool accumulation ----------------
__global__ void k_pool(const int* __restrict__ batch, int n) {
    int w = (blockIdx.x * blockDim.x + threadIdx.x) >> 5;
    int lane = threadIdx.x & 31;
    if (w >= n) return;
    int g = batch[w];
    float4 v = *(const float4*)&g_h[(size_t)w * 128 + lane * 4];
    atomicAdd((float4*)&g_pool[g * 128 + lane * 4], v);
    if (lane == 0) atomicAdd(&g_cnt[g], 1.0f);
}

// ---------------- final linear + sigmoid ----------------
__global__ void k_final(const float* __restrict__ Wlin, const float* __restrict__ blin,
                        float* __restrict__ out) {
    int g = blockIdx.x;
    int j = threadIdx.x;  // 128
    __shared__ float s0[128], s1[128];
    float cnt = fmaxf(g_cnt[g], 1.0f);
    float p = g_pool[g * 128 + j] / cnt;
    s0[j] = p * Wlin[j * 2 + 0];
    s1[j] = p * Wlin[j * 2 + 1];
    __syncthreads();
#pragma unroll
    for (int st = 64; st > 0; st >>= 1) {
        if (j < st) { s0[j] += s0[j + st]; s1[j] += s1[j + st]; }
        __syncthreads();
    }
    if (j == 0) {
        out[g * 2 + 0] = 1.0f / (1.0f + __expf(-(s0[0] + blin[0])));
        out[g * 2 + 1] = 1.0f / (1.0f + __expf(-(s1[0] + blin[1])));
    }
}

// ---------------- host orchestration ----------------
extern "C" void kernel_launch(void* const* d_in, const int* in_sizes, int n_in,
                              void* d_out, int out_size) {
    const float* x     = (const float*)d_in[0];
    const int*   ei    = (const int*)d_in[1];     // int32: JAX x64 disabled
    const int*   batch = (const int*)d_in[2];
    const float* Wl[3] = { (const float*)d_in[3], (const float*)d_in[7],  (const float*)d_in[11] };
    const float* As[3] = { (const float*)d_in[4], (const float*)d_in[8],  (const float*)d_in[12] };
    const float* Ad[3] = { (const float*)d_in[5], (const float*)d_in[9],  (const float*)d_in[13] };
    const float* Bs[3] = { (const float*)d_in[6], (const float*)d_in[10], (const float*)d_in[14] };
    const float* Wlin  = (const float*)d_in[15];
    const float* blin  = (const float*)d_in[16];
    float* out = (float*)d_out;

    int n  = in_sizes[0];               // nodes
    int E  = in_sizes[1] / 2;           // real edges
    int ET = E + n;                     // + self loops
    if (n > NMAX) n = NMAX;
    if (ET > ETMAX) ET = ETMAX;

    const int n32 = n * 32;             // float4 slots per feature buffer
    const int TB = 256;
    dim3 gN32((n32 + TB - 1) / TB);
    dim3 gN((n + TB - 1) / TB);
    dim3 gE((ET + TB - 1) / TB);
    dim3 gEW(((size_t)ET * 32 + TB - 1) / TB);  // warp per edge
    dim3 gNW((n * 32 + TB - 1) / TB);   // warp per node
    dim3 gG((n + 127) / 128);           // gemm node tiles

    for (int l = 0; l < 3; l++) {
        k_zero_out<<<gN32, TB>>>(n32);
        k_init_node<<<gN, TB>>>(n);
        if (l == 0) k_l1<<<gN32, TB>>>(x, Wl[0], n32);
        else        k_gemm<<<gG, TB>>>(Wl[l], n);
        k_attn<<<gNW, TB>>>(As[l], Ad[l], n);
        k_edge_max<<<gE, TB>>>(ei, E, ET);
        k_edge_den<<<gE, TB>>>(ei, E, ET);
        k_edge_agg<<<gEW, TB>>>(ei, E, ET);
        k_bias_relu<<<gN32, TB>>>(Bs[l], n32);
    }

    k_pool_init<<<(NG * HID + TB - 1) / TB, TB>>>();
    k_pool<<<gNW, TB>>>(batch, n);
    k_final<<<NG, 128>>>(Wlin, blin, out);
}

// round 3
// speedup vs baseline: 1.4796x; 1.4796x over previous
#include <cuda_runtime.h>
#include <cuda_bf16.h>
#include <math.h>

#define NMAX 50000
#define EMAX 600000
#define HID  128
#define NG   64

// ---------------- device scratch ----------------
__device__ __align__(16) float g_h [(size_t)NMAX * HID];
__device__ __align__(16) float g_xp[(size_t)NMAX * HID];
__device__ float g_als[NMAX];
__device__ float g_ald[NMAX];
__device__ __align__(16) float g_pool[NG * HID];
__device__ float g_cnt[NG];
__device__ float g_c[2];
__device__ int   g_deg[NMAX];
__device__ int   g_rowptr[NMAX + 1];
__device__ int   g_wptr[NMAX];
__device__ int   g_csrc[EMAX];

__device__ __forceinline__ float lrelu(float a) { return (a > 0.f) ? a : 0.2f * a; }

// ================= CSR build =================
__global__ void k_zero_deg(int n) {
    int i = blockIdx.x * blockDim.x + threadIdx.x;
    if (i < n) g_deg[i] = 0;
}
__global__ void k_hist(const int* __restrict__ ei, int E) {
    int e = blockIdx.x * blockDim.x + threadIdx.x;
    if (e < E) atomicAdd(&g_deg[ei[E + e]], 1);
}
// single-block exclusive scan of g_deg -> g_rowptr (+ copy to g_wptr)
__global__ void k_scan(int n) {
    __shared__ int warp_sums[32];
    __shared__ int s_carry;
    int tid = threadIdx.x, lane = tid & 31, wid = tid >> 5;
    if (tid == 0) s_carry = 0;
    __syncthreads();
    for (int base = 0; base < n; base += 1024) {
        int i = base + tid;
        int v = (i < n) ? g_deg[i] : 0;
        int x = v;
#pragma unroll
        for (int o = 1; o < 32; o <<= 1) {
            int y = __shfl_up_sync(0xffffffffu, x, o);
            if (lane >= o) x += y;
        }
        if (lane == 31) warp_sums[wid] = x;
        __syncthreads();
        if (wid == 0) {
            int w = warp_sums[lane];
#pragma unroll
            for (int o = 1; o < 32; o <<= 1) {
                int y = __shfl_up_sync(0xffffffffu, w, o);
                if (lane >= o) w += y;
            }
            warp_sums[lane] = w;
        }
        __syncthreads();
        int carry = s_carry;
        int excl = carry + (wid ? warp_sums[wid - 1] : 0) + x - v;
        if (i < n) { g_rowptr[i] = excl; g_wptr[i] = excl; }
        int total = warp_sums[31];
        __syncthreads();
        if (tid == 0) s_carry = carry + total;
        __syncthreads();
    }
    if (threadIdx.x == 0) g_rowptr[n] = s_carry;
}
__global__ void k_scatter(const int* __restrict__ ei, int E) {
    int e = blockIdx.x * blockDim.x + threadIdx.x;
    if (e >= E) return;
    int d = ei[E + e];
    int pos = atomicAdd(&g_wptr[d], 1);
    g_csrc[pos] = ei[e];
}

// ================= layer 1 =================
__global__ void k_l1c(const float* __restrict__ W1, const float* __restrict__ as1,
                      const float* __restrict__ ad1) {
    __shared__ float s0[128], s1[128];
    int j = threadIdx.x;
    float w = W1[j];
    s0[j] = w * as1[j];
    s1[j] = w * ad1[j];
    __syncthreads();
#pragma unroll
    for (int st = 64; st > 0; st >>= 1) {
        if (j < st) { s0[j] += s0[j + st]; s1[j] += s1[j + st]; }
        __syncthreads();
    }
    if (j == 0) { g_c[0] = s0[0]; g_c[1] = s1[0]; }
}
__global__ void k_l1(const float* __restrict__ x, const float* __restrict__ W1, int n32) {
    int i = blockIdx.x * blockDim.x + threadIdx.x;
    if (i >= n32) return;
    int node = i >> 5;
    float xv = x[node];
    float4 w = ((const float4*)W1)[i & 31];
    ((float4*)g_xp)[i] = make_float4(xv * w.x, xv * w.y, xv * w.z, xv * w.w);
    if ((i & 31) == 0) {
        g_als[node] = xv * g_c[0];
        g_ald[node] = xv * g_c[1];
    }
}

// ================= GEMM (+ fused attn scalars) =================
__global__ __launch_bounds__(256, 2) void k_gemm(const float* __restrict__ W,
                                                 const float* __restrict__ asv,
                                                 const float* __restrict__ adv, int n) {
    __shared__ float sA[16][128];
    __shared__ float sB[16][128];
    __shared__ float sS[128], sD[128];
    const int tid = threadIdx.x;
    const int row0 = blockIdx.x * 128;
    const int tx = tid & 15, ty = tid >> 4;
    float acc[8][8];
#pragma unroll
    for (int i = 0; i < 8; i++)
#pragma unroll
        for (int j = 0; j < 8; j++) acc[i][j] = 0.f;

    if (tid < 128) { sS[tid] = 0.f; sD[tid] = 0.f; }

    for (int k0 = 0; k0 < 128; k0 += 16) {
#pragma unroll
        for (int p = 0; p < 2; p++) {
            int r = (tid >> 2) + p * 64;
            int c = (tid & 3) * 4;
            float4 v = make_float4(0.f, 0.f, 0.f, 0.f);
            if (row0 + r < n)
                v = *(const float4*)&g_h[(size_t)(row0 + r) * 128 + k0 + c];
            sA[c + 0][r] = v.x; sA[c + 1][r] = v.y;
            sA[c + 2][r] = v.z; sA[c + 3][r] = v.w;
        }
#pragma unroll
        for (int p = 0; p < 2; p++) {
            int kk = (tid >> 5) + p * 8;
            int j = (tid & 31) * 4;
            *(float4*)&sB[kk][j] = *(const float4*)&W[(size_t)(k0 + kk) * 128 + j];
        }
        __syncthreads();
#pragma unroll
        for (int kk = 0; kk < 16; kk++) {
            float a[8], b[8];
            *(float4*)&a[0] = *(float4*)&sA[kk][ty * 8];
            *(float4*)&a[4] = *(float4*)&sA[kk][ty * 8 + 4];
            *(float4*)&b[0] = *(float4*)&sB[kk][tx * 8];
            *(float4*)&b[4] = *(float4*)&sB[kk][tx * 8 + 4];
#pragma unroll
            for (int i = 0; i < 8; i++)
#pragma unroll
                for (int j = 0; j < 8; j++) acc[i][j] += a[i] * b[j];
        }
        __syncthreads();
    }

    // fused attention scalars: partial dot of each output row with a_src / a_dst
    float av[8], dv[8];
#pragma unroll
    for (int j = 0; j < 8; j++) { av[j] = asv[tx * 8 + j]; dv[j] = adv[tx * 8 + j]; }
#pragma unroll
    for (int i = 0; i < 8; i++) {
        int r = row0 + ty * 8 + i;
        if (r < n) {
            *(float4*)&g_xp[(size_t)r * 128 + tx * 8]     = *(float4*)&acc[i][0];
            *(float4*)&g_xp[(size_t)r * 128 + tx * 8 + 4] = *(float4*)&acc[i][4];
        }
        float ps = 0.f, pd = 0.f;
#pragma unroll
        for (int j = 0; j < 8; j++) { ps += acc[i][j] * av[j]; pd += acc[i][j] * dv[j]; }
        atomicAdd(&sS[ty * 8 + i], ps);
        atomicAdd(&sD[ty * 8 + i], pd);
    }
    __syncthreads();
    if (tid < 128 && row0 + tid < n) {
        g_als[row0 + tid] = sS[tid];
        g_ald[row0 + tid] = sD[tid];
    }
}

// ================= fused GAT softmax-aggregate (warp per dst node) =================
__global__ __launch_bounds__(256) void k_gat_agg(const float* __restrict__ b, int n) {
    int w = (blockIdx.x * blockDim.x + threadIdx.x) >> 5;
    int lane = threadIdx.x & 31;
    if (w >= n) return;
    int row = g_rowptr[w], end = g_rowptr[w + 1];
    float ald_d = g_ald[w];
    float a_self = lrelu(g_als[w] + ald_d);

    // phase 1: segment max (self loop included)
    float m = a_self;
    for (int e = row + lane; e < end; e += 32)
        m = fmaxf(m, lrelu(__ldg(&g_als[g_csrc[e]]) + ald_d));
#pragma unroll
    for (int o = 16; o > 0; o >>= 1)
        m = fmaxf(m, __shfl_xor_sync(0xffffffffu, m, o));

    // phase 2: denominator
    float den = (lane == 0) ? __expf(a_self - m) : 0.f;
    for (int e = row + lane; e < end; e += 32)
        den += __expf(lrelu(__ldg(&g_als[g_csrc[e]]) + ald_d) - m);
#pragma unroll
    for (int o = 16; o > 0; o >>= 1)
        den += __shfl_xor_sync(0xffffffffu, den, o);
    float rden = 1.0f / den;

    // phase 3: feature accumulation (lane owns 4 features)
    const float4* xpv = (const float4*)g_xp;
    float cself = __expf(a_self - m) * rden;
    float4 acc = xpv[(size_t)w * 32 + lane];
    acc.x *= cself; acc.y *= cself; acc.z *= cself; acc.w *= cself;
#pragma unroll 2
    for (int j = row; j < end; j++) {
        int s = g_csrc[j];
        float coef = __expf(lrelu(g_als[s] + ald_d) - m) * rden;
        float4 v = xpv[(size_t)s * 32 + lane];
        acc.x += coef * v.x; acc.y += coef * v.y;
        acc.z += coef * v.z; acc.w += coef * v.w;
    }
    float4 bb = ((const float4*)b)[lane];
    acc.x = fmaxf(acc.x + bb.x, 0.f);
    acc.y = fmaxf(acc.y + bb.y, 0.f);
    acc.z = fmaxf(acc.z + bb.z, 0.f);
    acc.w = fmaxf(acc.w + bb.w, 0.f);
    ((float4*)g_h)[(size_t)w * 32 + lane] = acc;
}

// ================= pooling + head =================
__global__ void k_pool_init() {
    int i = blockIdx.x * blockDim.x + threadIdx.x;
    if (i < NG * HID) g_pool[i] = 0.0f;
    if (i < NG) g_cnt[i] = 0.0f;
}
__global__ void k_pool(const int* __restrict__ batch, int n) {
    int w = (blockIdx.x * blockDim.x + threadIdx.x) >> 5;
    int lane = threadIdx.x & 31;
    if (w >= n) return;
    int g = batch[w];
    float4 v = *(const float4*)&g_h[(size_t)w * 128 + lane * 4];
    atomicAdd((float4*)&g_pool[g * 128 + lane * 4], v);
    if (lane == 0) atomicAdd(&g_cnt[g], 1.0f);
}
__global__ void k_final(const float* __restrict__ Wlin, const float* __restrict__ blin,
                        float* __restrict__ out) {
    int g = blockIdx.x;
    int j = threadIdx.x;
    __shared__ float s0[128], s1[128];
    float cnt = fmaxf(g_cnt[g], 1.0f);
    float p = g_pool[g * 128 + j] / cnt;
    s0[j] = p * Wlin[j * 2 + 0];
    s1[j] = p * Wlin[j * 2 + 1];
    __syncthreads();
#pragma unroll
    for (int st = 64; st > 0; st >>= 1) {
        if (j < st) { s0[j] += s0[j + st]; s1[j] += s1[j + st]; }
        __syncthreads();
    }
    if (j == 0) {
        out[g * 2 + 0] = 1.0f / (1.0f + __expf(-(s0[0] + blin[0])));
        out[g * 2 + 1] = 1.0f / (1.0f + __expf(-(s1[0] + blin[1])));
    }
}

// ================= host =================
extern "C" void kernel_launch(void* const* d_in, const int* in_sizes, int n_in,
                              void* d_out, int out_size) {
    const float* x     = (const float*)d_in[0];
    const int*   ei    = (const int*)d_in[1];
    const int*   batch = (const int*)d_in[2];
    const float* Wl[3] = { (const float*)d_in[3], (const float*)d_in[7],  (const float*)d_in[11] };
    const float* As[3] = { (const float*)d_in[4], (const float*)d_in[8],  (const float*)d_in[12] };
    const float* Ad[3] = { (const float*)d_in[5], (const float*)d_in[9],  (const float*)d_in[13] };
    const float* Bs[3] = { (const float*)d_in[6], (const float*)d_in[10], (const float*)d_in[14] };
    const float* Wlin  = (const float*)d_in[15];
    const float* blin  = (const float*)d_in[16];
    float* out = (float*)d_out;

    int n = in_sizes[0];
    int E = in_sizes[1] / 2;
    if (n > NMAX) n = NMAX;
    if (E > EMAX) E = EMAX;

    const int TB = 256;
    const int n32 = n * 32;
    dim3 gN32((n32 + TB - 1) / TB);
    dim3 gN((n + TB - 1) / TB);
    dim3 gE((E + TB - 1) / TB);
    dim3 gNW(((size_t)n * 32 + TB - 1) / TB);
    dim3 gG((n + 127) / 128);

    // CSR build (once per call)
    k_zero_deg<<<gN, TB>>>(n);
    k_hist<<<gE, TB>>>(ei, E);
    k_scan<<<1, 1024>>>(n);
    k_scatter<<<gE, TB>>>(ei, E);

    // layer 1
    k_l1c<<<1, 128>>>(Wl[0], As[0], Ad[0]);
    k_l1<<<gN32, TB>>>(x, Wl[0], n32);
    k_gat_agg<<<gNW, TB>>>(Bs[0], n);
    // layers 2,3
    for (int l = 1; l < 3; l++) {
        k_gemm<<<gG, TB>>>(Wl[l], As[l], Ad[l], n);
        k_gat_agg<<<gNW, TB>>>(Bs[l], n);
    }

    k_pool_init<<<(NG * HID + TB - 1) / TB, TB>>>();
    k_pool<<<gNW, TB>>>(batch, n);
    k_final<<<NG, 128>>>(Wlin, blin, out);
}

// round 4
// speedup vs baseline: 1.6174x; 1.0932x over previous
#include <cuda_runtime.h>
#include <cuda_bf16.h>
#include <math.h>

#define NMAX 50000
#define EMAX 600000
#define HID  128
#define NG   64
#define FULLMASK 0xffffffffu

// ---------------- device scratch ----------------
__device__ __align__(16) float g_h [(size_t)NMAX * HID];
__device__ __align__(16) float g_xp[(size_t)NMAX * HID];
__device__ float g_als[NMAX];
__device__ float g_ald[NMAX];
__device__ __align__(16) float g_pool[NG * HID];
__device__ float g_cnt[NG];
__device__ float g_c[2];
__device__ int   g_deg[NMAX];
__device__ int   g_rowptr[NMAX + 1];
__device__ int   g_wptr[NMAX];
__device__ int   g_csrc[EMAX];
__device__ int   g_bsum[64];
__device__ int   g_total;

__device__ __forceinline__ float lrelu(float a) { return (a > 0.f) ? a : 0.2f * a; }

// ================= CSR build =================
__global__ void k_hist(const int* __restrict__ ei, int E) {
    int e = blockIdx.x * blockDim.x + threadIdx.x;
    if (e < E) atomicAdd(&g_deg[ei[E + e]], 1);
}

// block-local exclusive scan over 1024-chunks; block total -> g_bsum
__global__ void k_scan_blk(int n) {
    __shared__ int warp_sums[32];
    int tid = threadIdx.x, lane = tid & 31, wid = tid >> 5;
    int i = blockIdx.x * 1024 + tid;
    int v = (i < n) ? g_deg[i] : 0;
    int x = v;
#pragma unroll
    for (int o = 1; o < 32; o <<= 1) {
        int y = __shfl_up_sync(FULLMASK, x, o);
        if (lane >= o) x += y;
    }
    if (lane == 31) warp_sums[wid] = x;
    __syncthreads();
    if (wid == 0) {
        int w = warp_sums[lane];
#pragma unroll
        for (int o = 1; o < 32; o <<= 1) {
            int y = __shfl_up_sync(FULLMASK, w, o);
            if (lane >= o) w += y;
        }
        warp_sums[lane] = w;
    }
    __syncthreads();
    int excl = (wid ? warp_sums[wid - 1] : 0) + x - v;
    if (i < n) g_rowptr[i] = excl;
    if (tid == 1023) g_bsum[blockIdx.x] = warp_sums[31];
}

// exclusive scan of up to 64 block sums (1 warp handles 2 each -> simple serial in smem)
__global__ void k_scan_top(int nb) {
    __shared__ int s[65];
    int tid = threadIdx.x;  // 64
    s[tid] = (tid < nb) ? g_bsum[tid] : 0;
    __syncthreads();
    if (tid == 0) {
        int run = 0;
        for (int i = 0; i < 64; i++) { int t = s[i]; s[i] = run; run += t; }
        s[64] = run;
        g_total = run;
    }
    __syncthreads();
    if (tid < nb) g_bsum[tid] = s[tid];
}

__global__ void k_scan_add(int n) {
    int i = blockIdx.x * 1024 + threadIdx.x;
    if (i < n) {
        int r = g_rowptr[i] + g_bsum[blockIdx.x];
        g_rowptr[i] = r;
        g_wptr[i] = r;
    }
    if (i == 0) g_rowptr[n] = g_total;
}

__global__ void k_scatter(const int* __restrict__ ei, int E) {
    int e = blockIdx.x * blockDim.x + threadIdx.x;
    if (e >= E) return;
    int d = ei[E + e];
    int pos = atomicAdd(&g_wptr[d], 1);
    g_csrc[pos] = ei[e];
}

// ================= layer 1 =================
__global__ void k_l1c(const float* __restrict__ W1, const float* __restrict__ as1,
                      const float* __restrict__ ad1) {
    __shared__ float s0[128], s1[128];
    int j = threadIdx.x;
    float w = W1[j];
    s0[j] = w * as1[j];
    s1[j] = w * ad1[j];
    __syncthreads();
#pragma unroll
    for (int st = 64; st > 0; st >>= 1) {
        if (j < st) { s0[j] += s0[j + st]; s1[j] += s1[j + st]; }
        __syncthreads();
    }
    if (j == 0) { g_c[0] = s0[0]; g_c[1] = s1[0]; }
}
__global__ void k_l1(const float* __restrict__ x, const float* __restrict__ W1, int n32) {
    int i = blockIdx.x * blockDim.x + threadIdx.x;
    if (i >= n32) return;
    int node = i >> 5;
    float xv = x[node];
    float4 w = ((const float4*)W1)[i & 31];
    ((float4*)g_xp)[i] = make_float4(xv * w.x, xv * w.y, xv * w.z, xv * w.w);
    if ((i & 31) == 0) {
        g_als[node] = xv * g_c[0];
        g_ald[node] = xv * g_c[1];
    }
}

// ================= GEMM (+ fused attn scalars) =================
__global__ __launch_bounds__(256, 2) void k_gemm(const float* __restrict__ W,
                                                 const float* __restrict__ asv,
                                                 const float* __restrict__ adv, int n) {
    __shared__ float sA[16][128];
    __shared__ float sB[16][128];
    __shared__ float sS[128], sD[128];
    const int tid = threadIdx.x;
    const int row0 = blockIdx.x * 128;
    const int tx = tid & 15, ty = tid >> 4;
    float acc[8][8];
#pragma unroll
    for (int i = 0; i < 8; i++)
#pragma unroll
        for (int j = 0; j < 8; j++) acc[i][j] = 0.f;

    if (tid < 128) { sS[tid] = 0.f; sD[tid] = 0.f; }

    for (int k0 = 0; k0 < 128; k0 += 16) {
#pragma unroll
        for (int p = 0; p < 2; p++) {
            int r = (tid >> 2) + p * 64;
            int c = (tid & 3) * 4;
            float4 v = make_float4(0.f, 0.f, 0.f, 0.f);
            if (row0 + r < n)
                v = *(const float4*)&g_h[(size_t)(row0 + r) * 128 + k0 + c];
            sA[c + 0][r] = v.x; sA[c + 1][r] = v.y;
            sA[c + 2][r] = v.z; sA[c + 3][r] = v.w;
        }
#pragma unroll
        for (int p = 0; p < 2; p++) {
            int kk = (tid >> 5) + p * 8;
            int j = (tid & 31) * 4;
            *(float4*)&sB[kk][j] = *(const float4*)&W[(size_t)(k0 + kk) * 128 + j];
        }
        __syncthreads();
#pragma unroll
        for (int kk = 0; kk < 16; kk++) {
            float a[8], b[8];
            *(float4*)&a[0] = *(float4*)&sA[kk][ty * 8];
            *(float4*)&a[4] = *(float4*)&sA[kk][ty * 8 + 4];
            *(float4*)&b[0] = *(float4*)&sB[kk][tx * 8];
            *(float4*)&b[4] = *(float4*)&sB[kk][tx * 8 + 4];
#pragma unroll
            for (int i = 0; i < 8; i++)
#pragma unroll
                for (int j = 0; j < 8; j++) acc[i][j] += a[i] * b[j];
        }
        __syncthreads();
    }

    float av[8], dv[8];
#pragma unroll
    for (int j = 0; j < 8; j++) { av[j] = asv[tx * 8 + j]; dv[j] = adv[tx * 8 + j]; }
#pragma unroll
    for (int i = 0; i < 8; i++) {
        int r = row0 + ty * 8 + i;
        if (r < n) {
            *(float4*)&g_xp[(size_t)r * 128 + tx * 8]     = *(float4*)&acc[i][0];
            *(float4*)&g_xp[(size_t)r * 128 + tx * 8 + 4] = *(float4*)&acc[i][4];
        }
        float ps = 0.f, pd = 0.f;
#pragma unroll
        for (int j = 0; j < 8; j++) { ps += acc[i][j] * av[j]; pd += acc[i][j] * dv[j]; }
        atomicAdd(&sS[ty * 8 + i], ps);
        atomicAdd(&sD[ty * 8 + i], pd);
    }
    __syncthreads();
    if (tid < 128 && row0 + tid < n) {
        g_als[row0 + tid] = sS[tid];
        g_ald[row0 + tid] = sD[tid];
    }
}

// ================= fused GAT softmax-aggregate (warp per dst node) =================
__global__ __launch_bounds__(256) void k_gat_agg(const float* __restrict__ b, int n) {
    int w = (blockIdx.x * blockDim.x + threadIdx.x) >> 5;
    int lane = threadIdx.x & 31;
    if (w >= n) return;
    int row = g_rowptr[w], end = g_rowptr[w + 1];
    int cnt = end - row;
    float ald_d = g_ald[w];
    float a_self = lrelu(g_als[w] + ald_d);
    const float4* xpv = (const float4*)g_xp;
    float4 acc;

    if (cnt <= 32) {
        // single gather: each lane owns at most one in-edge
        int s_reg = 0;
        float a_reg = -1e30f;
        if (lane < cnt) {
            s_reg = g_csrc[row + lane];
            a_reg = lrelu(g_als[s_reg] + ald_d);
        }
        float m = fmaxf(a_reg, a_self);
#pragma unroll
        for (int o = 16; o > 0; o >>= 1)
            m = fmaxf(m, __shfl_xor_sync(FULLMASK, m, o));
        float p = (lane < cnt) ? __expf(a_reg - m) : 0.f;
        float den = p;
#pragma unroll
        for (int o = 16; o > 0; o >>= 1)
            den += __shfl_xor_sync(FULLMASK, den, o);
        float eself = __expf(a_self - m);
        float rden = 1.0f / (den + eself);
        p *= rden;

        float cself = eself * rden;
        acc = xpv[(size_t)w * 32 + lane];
        acc.x *= cself; acc.y *= cself; acc.z *= cself; acc.w *= cself;
        for (int j = 0; j < cnt; j++) {
            float coef = __shfl_sync(FULLMASK, p, j);
            int s = __shfl_sync(FULLMASK, s_reg, j);
            float4 v = xpv[(size_t)s * 32 + lane];
            acc.x += coef * v.x; acc.y += coef * v.y;
            acc.z += coef * v.z; acc.w += coef * v.w;
        }
    } else {
        // generic fallback (rare: deg > 32)
        float m = a_self;
        for (int e = row + lane; e < end; e += 32)
            m = fmaxf(m, lrelu(__ldg(&g_als[g_csrc[e]]) + ald_d));
#pragma unroll
        for (int o = 16; o > 0; o >>= 1)
            m = fmaxf(m, __shfl_xor_sync(FULLMASK, m, o));
        float den = (lane == 0) ? __expf(a_self - m) : 0.f;
        for (int e = row + lane; e < end; e += 32)
            den += __expf(lrelu(__ldg(&g_als[g_csrc[e]]) + ald_d) - m);
#pragma unroll
        for (int o = 16; o > 0; o >>= 1)
            den += __shfl_xor_sync(FULLMASK, den, o);
        float rden = 1.0f / den;
        float cself = __expf(a_self - m) * rden;
        acc = xpv[(size_t)w * 32 + lane];
        acc.x *= cself; acc.y *= cself; acc.z *= cself; acc.w *= cself;
        for (int j = row; j < end; j++) {
            int s = g_csrc[j];
            float coef = __expf(lrelu(g_als[s] + ald_d) - m) * rden;
            float4 v = xpv[(size_t)s * 32 + lane];
            acc.x += coef * v.x; acc.y += coef * v.y;
            acc.z += coef * v.z; acc.w += coef * v.w;
        }
    }

    float4 bb = ((const float4*)b)[lane];
    acc.x = fmaxf(acc.x + bb.x, 0.f);
    acc.y = fmaxf(acc.y + bb.y, 0.f);
    acc.z = fmaxf(acc.z + bb.z, 0.f);
    acc.w = fmaxf(acc.w + bb.w, 0.f);
    ((float4*)g_h)[(size_t)w * 32 + lane] = acc;
}

// ================= pooling + head =================
__global__ void k_pool(const int* __restrict__ batch, int n) {
    int w = (blockIdx.x * blockDim.x + threadIdx.x) >> 5;
    int lane = threadIdx.x & 31;
    if (w >= n) return;
    int g = batch[w];
    float4 v = *(const float4*)&g_h[(size_t)w * 128 + lane * 4];
    atomicAdd((float4*)&g_pool[g * 128 + lane * 4], v);
    if (lane == 0) atomicAdd(&g_cnt[g], 1.0f);
}
__global__ void k_final(const float* __restrict__ Wlin, const float* __restrict__ blin,
                        float* __restrict__ out) {
    int g = blockIdx.x;
    int j = threadIdx.x;
    __shared__ float s0[128], s1[128];
    float cnt = fmaxf(g_cnt[g], 1.0f);
    float p = g_pool[g * 128 + j] / cnt;
    s0[j] = p * Wlin[j * 2 + 0];
    s1[j] = p * Wlin[j * 2 + 1];
    __syncthreads();
#pragma unroll
    for (int st = 64; st > 0; st >>= 1) {
        if (j < st) { s0[j] += s0[j + st]; s1[j] += s1[j + st]; }
        __syncthreads();
    }
    if (j == 0) {
        out[g * 2 + 0] = 1.0f / (1.0f + __expf(-(s0[0] + blin[0])));
        out[g * 2 + 1] = 1.0f / (1.0f + __expf(-(s1[0] + blin[1])));
    }
}

// ================= host =================
extern "C" void kernel_launch(void* const* d_in, const int* in_sizes, int n_in,
                              void* d_out, int out_size) {
    const float* x     = (const float*)d_in[0];
    const int*   ei    = (const int*)d_in[1];
    const int*   batch = (const int*)d_in[2];
    const float* Wl[3] = { (const float*)d_in[3], (const float*)d_in[7],  (const float*)d_in[11] };
    const float* As[3] = { (const float*)d_in[4], (const float*)d_in[8],  (const float*)d_in[12] };
    const float* Ad[3] = { (const float*)d_in[5], (const float*)d_in[9],  (const float*)d_in[13] };
    const float* Bs[3] = { (const float*)d_in[6], (const float*)d_in[10], (const float*)d_in[14] };
    const float* Wlin  = (const float*)d_in[15];
    const float* blin  = (const float*)d_in[16];
    float* out = (float*)d_out;

    int n = in_sizes[0];
    int E = in_sizes[1] / 2;
    if (n > NMAX) n = NMAX;
    if (E > EMAX) E = EMAX;

    const int TB = 256;
    const int n32 = n * 32;
    dim3 gN32((n32 + TB - 1) / TB);
    dim3 gE((E + TB - 1) / TB);
    dim3 gNW(((size_t)n * 32 + TB - 1) / TB);
    dim3 gG((n + 127) / 128);
    int nBlk = (n + 1023) / 1024;

    void *p_deg, *p_pool, *p_cnt;
    cudaGetSymbolAddress(&p_deg, g_deg);
    cudaGetSymbolAddress(&p_pool, g_pool);
    cudaGetSymbolAddress(&p_cnt, g_cnt);

    // CSR build
    cudaMemsetAsync(p_deg, 0, (size_t)n * sizeof(int));
    k_hist<<<gE, TB>>>(ei, E);
    k_scan_blk<<<nBlk, 1024>>>(n);
    k_scan_top<<<1, 64>>>(nBlk);
    k_scan_add<<<nBlk, 1024>>>(n);
    k_scatter<<<gE, TB>>>(ei, E);

    // layer 1
    k_l1c<<<1, 128>>>(Wl[0], As[0], Ad[0]);
    k_l1<<<gN32, TB>>>(x, Wl[0], n32);
    k_gat_agg<<<gNW, TB>>>(Bs[0], n);
    // layers 2,3
    for (int l = 1; l < 3; l++) {
        k_gemm<<<gG, TB>>>(Wl[l], As[l], Ad[l], n);
        k_gat_agg<<<gNW, TB>>>(Bs[l], n);
    }

    cudaMemsetAsync(p_pool, 0, (size_t)NG * HID * sizeof(float));
    cudaMemsetAsync(p_cnt, 0, (size_t)NG * sizeof(float));
    k_pool<<<gNW, TB>>>(batch, n);
    k_final<<<NG, 128>>>(Wlin, blin, out);
}

// round 5
// speedup vs baseline: 2.1868x; 1.3520x over previous
#include <cuda_runtime.h>
#include <cuda_bf16.h>
#include <math.h>
#include <stdint.h>

#define NMAX 50000
#define EMAX 600000
#define HID  128
#define NG   64
#define FULLMASK 0xffffffffu

#define PADW 136   // smem stride for W tile (conflict-free B frag reads)
#define PADA 36    // smem stride for A tile (conflict-free A frag reads)
#define GEMM_SMEM ((128 * PADW + 128 * PADA) * 4)

// ---------------- device scratch ----------------
__device__ __align__(16) float g_h [(size_t)NMAX * HID];
__device__ __align__(16) float g_xp[(size_t)NMAX * HID];
__device__ float g_als[NMAX];
__device__ float g_ald[NMAX];
__device__ __align__(16) float g_pool[NG * HID];
__device__ float g_cnt[NG];
__device__ float g_c[2];
__device__ int   g_deg[NMAX];
__device__ int   g_rowptr[NMAX + 1];
__device__ int   g_wptr[NMAX];
__device__ int   g_csrc[EMAX];
__device__ int   g_bsum[64];
__device__ int   g_total;

__device__ __forceinline__ float lrelu(float a) { return (a > 0.f) ? a : 0.2f * a; }

__device__ __forceinline__ float to_tf32(float x) {
    float r;
    asm("cvt.rna.tf32.f32 %0, %1;" : "=f"(r) : "f"(x));
    return r;
}

__device__ __forceinline__ void mma_tf32(float c[4], const uint32_t a[4],
                                         uint32_t b0, uint32_t b1) {
    asm volatile(
        "mma.sync.aligned.m16n8k8.row.col.f32.tf32.tf32.f32 "
        "{%0,%1,%2,%3}, {%4,%5,%6,%7}, {%8,%9}, {%0,%1,%2,%3};"
        : "+f"(c[0]), "+f"(c[1]), "+f"(c[2]), "+f"(c[3])
        : "r"(a[0]), "r"(a[1]), "r"(a[2]), "r"(a[3]), "r"(b0), "r"(b1));
}

// ================= CSR build =================
__global__ void k_hist(const int* __restrict__ ei, int E) {
    int e = blockIdx.x * blockDim.x + threadIdx.x;
    if (e < E) atomicAdd(&g_deg[ei[E + e]], 1);
}

__global__ void k_scan_blk(int n) {
    __shared__ int warp_sums[32];
    int tid = threadIdx.x, lane = tid & 31, wid = tid >> 5;
    int i = blockIdx.x * 1024 + tid;
    int v = (i < n) ? g_deg[i] : 0;
    int x = v;
#pragma unroll
    for (int o = 1; o < 32; o <<= 1) {
        int y = __shfl_up_sync(FULLMASK, x, o);
        if (lane >= o) x += y;
    }
    if (lane == 31) warp_sums[wid] = x;
    __syncthreads();
    if (wid == 0) {
        int w = warp_sums[lane];
#pragma unroll
        for (int o = 1; o < 32; o <<= 1) {
            int y = __shfl_up_sync(FULLMASK, w, o);
            if (lane >= o) w += y;
        }
        warp_sums[lane] = w;
    }
    __syncthreads();
    int excl = (wid ? warp_sums[wid - 1] : 0) + x - v;
    if (i < n) g_rowptr[i] = excl;
    if (tid == 1023) g_bsum[blockIdx.x] = warp_sums[31];
}

__global__ void k_scan_top(int nb) {
    __shared__ int s[65];
    int tid = threadIdx.x;  // 64
    s[tid] = (tid < nb) ? g_bsum[tid] : 0;
    __syncthreads();
    if (tid == 0) {
        int run = 0;
        for (int i = 0; i < 64; i++) { int t = s[i]; s[i] = run; run += t; }
        s[64] = run;
        g_total = run;
    }
    __syncthreads();
    if (tid < nb) g_bsum[tid] = s[tid];
}

__global__ void k_scan_add(int n) {
    int i = blockIdx.x * 1024 + threadIdx.x;
    if (i < n) {
        int r = g_rowptr[i] + g_bsum[blockIdx.x];
        g_rowptr[i] = r;
        g_wptr[i] = r;
    }
    if (i == 0) g_rowptr[n] = g_total;
}

__global__ void k_scatter(const int* __restrict__ ei, int E) {
    int e = blockIdx.x * blockDim.x + threadIdx.x;
    if (e >= E) return;
    int d = ei[E + e];
    int pos = atomicAdd(&g_wptr[d], 1);
    g_csrc[pos] = ei[e];
}

// ================= layer 1 =================
__global__ void k_l1c(const float* __restrict__ W1, const float* __restrict__ as1,
                      const float* __restrict__ ad1) {
    __shared__ float s0[128], s1[128];
    int j = threadIdx.x;
    float w = W1[j];
    s0[j] = w * as1[j];
    s1[j] = w * ad1[j];
    __syncthreads();
#pragma unroll
    for (int st = 64; st > 0; st >>= 1) {
        if (j < st) { s0[j] += s0[j + st]; s1[j] += s1[j + st]; }
        __syncthreads();
    }
    if (j == 0) { g_c[0] = s0[0]; g_c[1] = s1[0]; }
}
__global__ void k_l1(const float* __restrict__ x, const float* __restrict__ W1, int n32) {
    int i = blockIdx.x * blockDim.x + threadIdx.x;
    if (i >= n32) return;
    int node = i >> 5;
    float xv = x[node];
    float4 w = ((const float4*)W1)[i & 31];
    ((float4*)g_xp)[i] = make_float4(xv * w.x, xv * w.y, xv * w.z, xv * w.w);
    if ((i & 31) == 0) {
        g_als[node] = xv * g_c[0];
        g_ald[node] = xv * g_c[1];
    }
}

// ================= tensor-core GEMM (TF32 mma) + fused attn scalars =================
// block: 256 threads = 8 warps; tile 128 rows x 128 cols; warp = 32 rows x 64 cols
__global__ __launch_bounds__(256, 2) void k_gemm_tc(const float* __restrict__ W,
                                                    const float* __restrict__ asv,
                                                    const float* __restrict__ adv, int n) {
    extern __shared__ float smem[];
    float* sW = smem;                 // [128][PADW]
    float* sA = smem + 128 * PADW;    // [128][PADA]
    __shared__ float sS[128], sD[128];

    const int tid = threadIdx.x;
    const int row0 = blockIdx.x * 128;
    const int wid = tid >> 5, lane = tid & 31;
    const int wr = wid & 3;           // row strip 0..3 (32 rows each)
    const int wc = wid >> 2;          // col half 0..1 (64 cols each)
    const int gid = lane >> 2, tig = lane & 3;

    if (tid < 128) { sS[tid] = 0.f; sD[tid] = 0.f; }

    // stage W (tf32)
    for (int i = tid; i < 4096; i += 256) {
        int k = i >> 5;             // 32 float4 per row
        int c = (i & 31) * 4;
        float4 v = *(const float4*)&W[k * 128 + c];
        sW[k * PADW + c + 0] = to_tf32(v.x);
        sW[k * PADW + c + 1] = to_tf32(v.y);
        sW[k * PADW + c + 2] = to_tf32(v.z);
        sW[k * PADW + c + 3] = to_tf32(v.w);
    }

    float acc[2][8][4];
#pragma unroll
    for (int mt = 0; mt < 2; mt++)
#pragma unroll
        for (int j = 0; j < 8; j++)
#pragma unroll
            for (int q = 0; q < 4; q++) acc[mt][j][q] = 0.f;

    for (int kc = 0; kc < 4; kc++) {
        // stage A chunk 128 rows x 32 k (tf32)
        __syncthreads();
        for (int i = tid; i < 1024; i += 256) {
            int r = i >> 3;
            int c = (i & 7) * 4;
            float4 v = make_float4(0.f, 0.f, 0.f, 0.f);
            if (row0 + r < n)
                v = *(const float4*)&g_h[(size_t)(row0 + r) * 128 + kc * 32 + c];
            sA[r * PADA + c + 0] = to_tf32(v.x);
            sA[r * PADA + c + 1] = to_tf32(v.y);
            sA[r * PADA + c + 2] = to_tf32(v.z);
            sA[r * PADA + c + 3] = to_tf32(v.w);
        }
        __syncthreads();

#pragma unroll
        for (int ks = 0; ks < 4; ks++) {
            int k0 = ks * 8;
            uint32_t a[2][4];
#pragma unroll
            for (int mt = 0; mt < 2; mt++) {
                int base = wr * 32 + mt * 16;
                a[mt][0] = __float_as_uint(sA[(base + gid)     * PADA + k0 + tig]);
                a[mt][1] = __float_as_uint(sA[(base + gid + 8) * PADA + k0 + tig]);
                a[mt][2] = __float_as_uint(sA[(base + gid)     * PADA + k0 + tig + 4]);
                a[mt][3] = __float_as_uint(sA[(base + gid + 8) * PADA + k0 + tig + 4]);
            }
#pragma unroll
            for (int j = 0; j < 8; j++) {
                int col = wc * 64 + j * 8 + gid;
                uint32_t b0 = __float_as_uint(sW[(kc * 32 + k0 + tig)     * PADW + col]);
                uint32_t b1 = __float_as_uint(sW[(kc * 32 + k0 + tig + 4) * PADW + col]);
                mma_tf32(acc[0][j], a[0], b0, b1);
                mma_tf32(acc[1][j], a[1], b0, b1);
            }
        }
    }
    __syncthreads();

    // epilogue: store xp + attention partial dots
#pragma unroll
    for (int mt = 0; mt < 2; mt++) {
        int lr0 = wr * 32 + mt * 16 + gid;      // local row (0..127)
        int lr1 = lr0 + 8;
        int r0 = row0 + lr0, r1 = row0 + lr1;
        float ps0 = 0.f, pd0 = 0.f, ps1 = 0.f, pd1 = 0.f;
#pragma unroll
        for (int j = 0; j < 8; j++) {
            int col = wc * 64 + j * 8 + tig * 2;
            float av0 = __ldg(&asv[col]), av1 = __ldg(&asv[col + 1]);
            float dv0 = __ldg(&adv[col]), dv1 = __ldg(&adv[col + 1]);
            if (r0 < n)
                *(float2*)&g_xp[(size_t)r0 * 128 + col] = make_float2(acc[mt][j][0], acc[mt][j][1]);
            if (r1 < n)
                *(float2*)&g_xp[(size_t)r1 * 128 + col] = make_float2(acc[mt][j][2], acc[mt][j][3]);
            ps0 += acc[mt][j][0] * av0 + acc[mt][j][1] * av1;
            pd0 += acc[mt][j][0] * dv0 + acc[mt][j][1] * dv1;
            ps1 += acc[mt][j][2] * av0 + acc[mt][j][3] * av1;
            pd1 += acc[mt][j][2] * dv0 + acc[mt][j][3] * dv1;
        }
        atomicAdd(&sS[lr0], ps0); atomicAdd(&sD[lr0], pd0);
        atomicAdd(&sS[lr1], ps1); atomicAdd(&sD[lr1], pd1);
    }
    __syncthreads();
    if (tid < 128 && row0 + tid < n) {
        g_als[row0 + tid] = sS[tid];
        g_ald[row0 + tid] = sD[tid];
    }
}

// ================= fused GAT softmax-aggregate (warp per dst node) =================
// EPILOGUE: 0 = bias+relu -> g_h ; 1 = bias+relu -> atomic pool (layer 3)
template <int EPILOGUE>
__global__ __launch_bounds__(256) void k_gat_agg(const float* __restrict__ b,
                                                 const int* __restrict__ batch, int n) {
    int w = (blockIdx.x * blockDim.x + threadIdx.x) >> 5;
    int lane = threadIdx.x & 31;
    if (w >= n) return;
    int row = g_rowptr[w], end = g_rowptr[w + 1];
    int cnt = end - row;
    float ald_d = g_ald[w];
    float a_self = lrelu(g_als[w] + ald_d);
    const float4* xpv = (const float4*)g_xp;
    float4 acc;

    if (cnt <= 32) {
        int s_reg = 0;
        float a_reg = -1e30f;
        if (lane < cnt) {
            s_reg = g_csrc[row + lane];
            a_reg = lrelu(g_als[s_reg] + ald_d);
        }
        float m = fmaxf(a_reg, a_self);
#pragma unroll
        for (int o = 16; o > 0; o >>= 1)
            m = fmaxf(m, __shfl_xor_sync(FULLMASK, m, o));
        float p = (lane < cnt) ? __expf(a_reg - m) : 0.f;
        float den = p;
#pragma unroll
        for (int o = 16; o > 0; o >>= 1)
            den += __shfl_xor_sync(FULLMASK, den, o);
        float eself = __expf(a_self - m);
        float rden = 1.0f / (den + eself);
        p *= rden;

        float cself = eself * rden;
        acc = xpv[(size_t)w * 32 + lane];
        acc.x *= cself; acc.y *= cself; acc.z *= cself; acc.w *= cself;
        for (int j = 0; j < cnt; j++) {
            float coef = __shfl_sync(FULLMASK, p, j);
            int s = __shfl_sync(FULLMASK, s_reg, j);
            float4 v = xpv[(size_t)s * 32 + lane];
            acc.x += coef * v.x; acc.y += coef * v.y;
            acc.z += coef * v.z; acc.w += coef * v.w;
        }
    } else {
        float m = a_self;
        for (int e = row + lane; e < end; e += 32)
            m = fmaxf(m, lrelu(__ldg(&g_als[g_csrc[e]]) + ald_d));
#pragma unroll
        for (int o = 16; o > 0; o >>= 1)
            m = fmaxf(m, __shfl_xor_sync(FULLMASK, m, o));
        float den = (lane == 0) ? __expf(a_self - m) : 0.f;
        for (int e = row + lane; e < end; e += 32)
            den += __expf(lrelu(__ldg(&g_als[g_csrc[e]]) + ald_d) - m);
#pragma unroll
        for (int o = 16; o > 0; o >>= 1)
            den += __shfl_xor_sync(FULLMASK, den, o);
        float rden = 1.0f / den;
        float cself = __expf(a_self - m) * rden;
        acc = xpv[(size_t)w * 32 + lane];
        acc.x *= cself; acc.y *= cself; acc.z *= cself; acc.w *= cself;
        for (int j = row; j < end; j++) {
            int s = g_csrc[j];
            float coef = __expf(lrelu(g_als[s] + ald_d) - m) * rden;
            float4 v = xpv[(size_t)s * 32 + lane];
            acc.x += coef * v.x; acc.y += coef * v.y;
            acc.z += coef * v.z; acc.w += coef * v.w;
        }
    }

    float4 bb = ((const float4*)b)[lane];
    acc.x = fmaxf(acc.x + bb.x, 0.f);
    acc.y = fmaxf(acc.y + bb.y, 0.f);
    acc.z = fmaxf(acc.z + bb.z, 0.f);
    acc.w = fmaxf(acc.w + bb.w, 0.f);

    if (EPILOGUE == 0) {
        ((float4*)g_h)[(size_t)w * 32 + lane] = acc;
    } else {
        int g = batch[w];
        atomicAdd((float4*)&g_pool[g * 128 + lane * 4], acc);
        if (lane == 0) atomicAdd(&g_cnt[g], 1.0f);
    }
}

// ================= head =================
__global__ void k_final(const float* __restrict__ Wlin, const float* __restrict__ blin,
                        float* __restrict__ out) {
    int g = blockIdx.x;
    int j = threadIdx.x;
    __shared__ float s0[128], s1[128];
    float cnt = fmaxf(g_cnt[g], 1.0f);
    float p = g_pool[g * 128 + j] / cnt;
    s0[j] = p * Wlin[j * 2 + 0];
    s1[j] = p * Wlin[j * 2 + 1];
    __syncthreads();
#pragma unroll
    for (int st = 64; st > 0; st >>= 1) {
        if (j < st) { s0[j] += s0[j + st]; s1[j] += s1[j + st]; }
        __syncthreads();
    }
    if (j == 0) {
        out[g * 2 + 0] = 1.0f / (1.0f + __expf(-(s0[0] + blin[0])));
        out[g * 2 + 1] = 1.0f / (1.0f + __expf(-(s1[0] + blin[1])));
    }
}

// ================= host =================
extern "C" void kernel_launch(void* const* d_in, const int* in_sizes, int n_in,
                              void* d_out, int out_size) {
    const float* x     = (const float*)d_in[0];
    const int*   ei    = (const int*)d_in[1];
    const int*   batch = (const int*)d_in[2];
    const float* Wl[3] = { (const float*)d_in[3], (const float*)d_in[7],  (const float*)d_in[11] };
    const float* As[3] = { (const float*)d_in[4], (const float*)d_in[8],  (const float*)d_in[12] };
    const float* Ad[3] = { (const float*)d_in[5], (const float*)d_in[9],  (const float*)d_in[13] };
    const float* Bs[3] = { (const float*)d_in[6], (const float*)d_in[10], (const float*)d_in[14] };
    const float* Wlin  = (const float*)d_in[15];
    const float* blin  = (const float*)d_in[16];
    float* out = (float*)d_out;

    int n = in_sizes[0];
    int E = in_sizes[1] / 2;
    if (n > NMAX) n = NMAX;
    if (E > EMAX) E = EMAX;

    const int TB = 256;
    const int n32 = n * 32;
    dim3 gN32((n32 + TB - 1) / TB);
    dim3 gE((E + TB - 1) / TB);
    dim3 gNW(((size_t)n * 32 + TB - 1) / TB);
    dim3 gG((n + 127) / 128);
    int nBlk = (n + 1023) / 1024;

    static bool attr_done = false;
    if (!attr_done) {
        cudaFuncSetAttribute(k_gemm_tc, cudaFuncAttributeMaxDynamicSharedMemorySize, GEMM_SMEM);
        attr_done = true;
    }

    void *p_deg, *p_pool, *p_cnt;
    cudaGetSymbolAddress(&p_deg, g_deg);
    cudaGetSymbolAddress(&p_pool, g_pool);
    cudaGetSymbolAddress(&p_cnt, g_cnt);

    // CSR build
    cudaMemsetAsync(p_deg, 0, (size_t)n * sizeof(int));
    k_hist<<<gE, TB>>>(ei, E);
    k_scan_blk<<<nBlk, 1024>>>(n);
    k_scan_top<<<1, 64>>>(nBlk);
    k_scan_add<<<nBlk, 1024>>>(n);
    k_scatter<<<gE, TB>>>(ei, E);

    // zero pool accumulators (consumed by layer-3 fused agg+pool)
    cudaMemsetAsync(p_pool, 0, (size_t)NG * HID * sizeof(float));
    cudaMemsetAsync(p_cnt, 0, (size_t)NG * sizeof(float));

    // layer 1
    k_l1c<<<1, 128>>>(Wl[0], As[0], Ad[0]);
    k_l1<<<gN32, TB>>>(x, Wl[0], n32);
    k_gat_agg<0><<<gNW, TB>>>(Bs[0], batch, n);
    // layer 2
    k_gemm_tc<<<gG, TB, GEMM_SMEM>>>(Wl[1], As[1], Ad[1], n);
    k_gat_agg<0><<<gNW, TB>>>(Bs[1], batch, n);
    // layer 3 (fused pool)
    k_gemm_tc<<<gG, TB, GEMM_SMEM>>>(Wl[2], As[2], Ad[2], n);
    k_gat_agg<1><<<gNW, TB>>>(Bs[2], batch, n);

    k_final<<<NG, 128>>>(Wlin, blin, out);
}

// round 6
// speedup vs baseline: 2.3781x; 1.0875x over previous
#include <cuda_runtime.h>
#include <cuda_fp16.h>
#include <math.h>
#include <stdint.h>

#define NMAX 50000
#define EMAX 600000
#define HID  128
#define NG   64
#define FULLMASK 0xffffffffu

#define PADW 136   // smem stride for W tile (conflict-free B frag reads)
#define PADA 36    // smem stride for A tile (conflict-free A frag reads)
#define GEMM_SMEM ((128 * PADW + 128 * PADA) * 4)

// ---------------- device scratch ----------------
__device__ __align__(16) float  g_h [(size_t)NMAX * HID];   // fp32 GEMM input
__device__ __align__(16) __half g_xph[(size_t)NMAX * HID];  // fp16 gather payload
__device__ float g_als[NMAX];
__device__ float g_ald[NMAX];
__device__ __align__(16) float g_pool[NG * HID];
__device__ float g_cnt[NG];
__device__ float g_c[2];
__device__ int   g_deg[NMAX];
__device__ int   g_rowptr[NMAX + 1];
__device__ int   g_wptr[NMAX];
__device__ int   g_csrc[EMAX];
__device__ int   g_bsum[64];
__device__ int   g_total;

__device__ __forceinline__ float lrelu(float a) { return (a > 0.f) ? a : 0.2f * a; }

__device__ __forceinline__ float to_tf32(float x) {
    float r;
    asm("cvt.rna.tf32.f32 %0, %1;" : "=f"(r) : "f"(x));
    return r;
}

__device__ __forceinline__ void mma_tf32(float c[4], const uint32_t a[4],
                                         uint32_t b0, uint32_t b1) {
    asm volatile(
        "mma.sync.aligned.m16n8k8.row.col.f32.tf32.tf32.f32 "
        "{%0,%1,%2,%3}, {%4,%5,%6,%7}, {%8,%9}, {%0,%1,%2,%3};"
        : "+f"(c[0]), "+f"(c[1]), "+f"(c[2]), "+f"(c[3])
        : "r"(a[0]), "r"(a[1]), "r"(a[2]), "r"(a[3]), "r"(b0), "r"(b1));
}

// unpack 4 halves (uint2) -> 4 floats
__device__ __forceinline__ float4 h4_to_f4(uint2 u) {
    float2 a = __half22float2(*(__half2*)&u.x);
    float2 b = __half22float2(*(__half2*)&u.y);
    return make_float4(a.x, a.y, b.x, b.y);
}

// ================= CSR build =================
__global__ void k_hist(const int* __restrict__ ei, int E) {
    int e = blockIdx.x * blockDim.x + threadIdx.x;
    if (e < E) atomicAdd(&g_deg[ei[E + e]], 1);
}

__global__ void k_scan_blk(int n) {
    __shared__ int warp_sums[32];
    int tid = threadIdx.x, lane = tid & 31, wid = tid >> 5;
    int i = blockIdx.x * 1024 + tid;
    int v = (i < n) ? g_deg[i] : 0;
    int x = v;
#pragma unroll
    for (int o = 1; o < 32; o <<= 1) {
        int y = __shfl_up_sync(FULLMASK, x, o);
        if (lane >= o) x += y;
    }
    if (lane == 31) warp_sums[wid] = x;
    __syncthreads();
    if (wid == 0) {
        int w = warp_sums[lane];
#pragma unroll
        for (int o = 1; o < 32; o <<= 1) {
            int y = __shfl_up_sync(FULLMASK, w, o);
            if (lane >= o) w += y;
        }
        warp_sums[lane] = w;
    }
    __syncthreads();
    int excl = (wid ? warp_sums[wid - 1] : 0) + x - v;
    if (i < n) g_rowptr[i] = excl;
    if (tid == 1023) g_bsum[blockIdx.x] = warp_sums[31];
}

__global__ void k_scan_top(int nb) {
    __shared__ int s[65];
    int tid = threadIdx.x;  // 64
    s[tid] = (tid < nb) ? g_bsum[tid] : 0;
    __syncthreads();
    if (tid == 0) {
        int run = 0;
        for (int i = 0; i < 64; i++) { int t = s[i]; s[i] = run; run += t; }
        s[64] = run;
        g_total = run;
    }
    __syncthreads();
    if (tid < nb) g_bsum[tid] = s[tid];
}

__global__ void k_scan_add(int n) {
    int i = blockIdx.x * 1024 + threadIdx.x;
    if (i < n) {
        int r = g_rowptr[i] + g_bsum[blockIdx.x];
        g_rowptr[i] = r;
        g_wptr[i] = r;
    }
    if (i == 0) g_rowptr[n] = g_total;
}

__global__ void k_scatter(const int* __restrict__ ei, int E) {
    int e = blockIdx.x * blockDim.x + threadIdx.x;
    if (e >= E) return;
    int d = ei[E + e];
    int pos = atomicAdd(&g_wptr[d], 1);
    g_csrc[pos] = ei[e];
}

// ================= layer 1 =================
__global__ void k_l1c(const float* __restrict__ W1, const float* __restrict__ as1,
                      const float* __restrict__ ad1) {
    __shared__ float s0[128], s1[128];
    int j = threadIdx.x;
    float w = W1[j];
    s0[j] = w * as1[j];
    s1[j] = w * ad1[j];
    __syncthreads();
#pragma unroll
    for (int st = 64; st > 0; st >>= 1) {
        if (j < st) { s0[j] += s0[j + st]; s1[j] += s1[j + st]; }
        __syncthreads();
    }
    if (j == 0) { g_c[0] = s0[0]; g_c[1] = s1[0]; }
}
__global__ void k_l1(const float* __restrict__ x, const float* __restrict__ W1, int n32) {
    int i = blockIdx.x * blockDim.x + threadIdx.x;
    if (i >= n32) return;
    int node = i >> 5;
    float xv = x[node];
    float4 w = ((const float4*)W1)[i & 31];
    uint2 st;
    *(__half2*)&st.x = __floats2half2_rn(xv * w.x, xv * w.y);
    *(__half2*)&st.y = __floats2half2_rn(xv * w.z, xv * w.w);
    ((uint2*)g_xph)[i] = st;
    if ((i & 31) == 0) {
        g_als[node] = xv * g_c[0];
        g_ald[node] = xv * g_c[1];
    }
}

// ================= tensor-core GEMM (TF32 mma) + fused attn scalars =================
__global__ __launch_bounds__(256, 2) void k_gemm_tc(const float* __restrict__ W,
                                                    const float* __restrict__ asv,
                                                    const float* __restrict__ adv, int n) {
    extern __shared__ float smem[];
    float* sW = smem;                 // [128][PADW]
    float* sA = smem + 128 * PADW;    // [128][PADA]
    __shared__ float sS[128], sD[128];

    const int tid = threadIdx.x;
    const int row0 = blockIdx.x * 128;
    const int wid = tid >> 5, lane = tid & 31;
    const int wr = wid & 3;
    const int wc = wid >> 2;
    const int gid = lane >> 2, tig = lane & 3;

    if (tid < 128) { sS[tid] = 0.f; sD[tid] = 0.f; }

    for (int i = tid; i < 4096; i += 256) {
        int k = i >> 5;
        int c = (i & 31) * 4;
        float4 v = *(const float4*)&W[k * 128 + c];
        sW[k * PADW + c + 0] = to_tf32(v.x);
        sW[k * PADW + c + 1] = to_tf32(v.y);
        sW[k * PADW + c + 2] = to_tf32(v.z);
        sW[k * PADW + c + 3] = to_tf32(v.w);
    }

    float acc[2][8][4];
#pragma unroll
    for (int mt = 0; mt < 2; mt++)
#pragma unroll
        for (int j = 0; j < 8; j++)
#pragma unroll
            for (int q = 0; q < 4; q++) acc[mt][j][q] = 0.f;

    for (int kc = 0; kc < 4; kc++) {
        __syncthreads();
        for (int i = tid; i < 1024; i += 256) {
            int r = i >> 3;
            int c = (i & 7) * 4;
            float4 v = make_float4(0.f, 0.f, 0.f, 0.f);
            if (row0 + r < n)
                v = *(const float4*)&g_h[(size_t)(row0 + r) * 128 + kc * 32 + c];
            sA[r * PADA + c + 0] = to_tf32(v.x);
            sA[r * PADA + c + 1] = to_tf32(v.y);
            sA[r * PADA + c + 2] = to_tf32(v.z);
            sA[r * PADA + c + 3] = to_tf32(v.w);
        }
        __syncthreads();

#pragma unroll
        for (int ks = 0; ks < 4; ks++) {
            int k0 = ks * 8;
            uint32_t a[2][4];
#pragma unroll
            for (int mt = 0; mt < 2; mt++) {
                int base = wr * 32 + mt * 16;
                a[mt][0] = __float_as_uint(sA[(base + gid)     * PADA + k0 + tig]);
                a[mt][1] = __float_as_uint(sA[(base + gid + 8) * PADA + k0 + tig]);
                a[mt][2] = __float_as_uint(sA[(base + gid)     * PADA + k0 + tig + 4]);
                a[mt][3] = __float_as_uint(sA[(base + gid + 8) * PADA + k0 + tig + 4]);
            }
#pragma unroll
            for (int j = 0; j < 8; j++) {
                int col = wc * 64 + j * 8 + gid;
                uint32_t b0 = __float_as_uint(sW[(kc * 32 + k0 + tig)     * PADW + col]);
                uint32_t b1 = __float_as_uint(sW[(kc * 32 + k0 + tig + 4) * PADW + col]);
                mma_tf32(acc[0][j], a[0], b0, b1);
                mma_tf32(acc[1][j], a[1], b0, b1);
            }
        }
    }
    __syncthreads();

    // epilogue: store xp (fp16) + attention partial dots (fp32)
#pragma unroll
    for (int mt = 0; mt < 2; mt++) {
        int lr0 = wr * 32 + mt * 16 + gid;
        int lr1 = lr0 + 8;
        int r0 = row0 + lr0, r1 = row0 + lr1;
        float ps0 = 0.f, pd0 = 0.f, ps1 = 0.f, pd1 = 0.f;
#pragma unroll
        for (int j = 0; j < 8; j++) {
            int col = wc * 64 + j * 8 + tig * 2;
            float av0 = __ldg(&asv[col]), av1 = __ldg(&asv[col + 1]);
            float dv0 = __ldg(&adv[col]), dv1 = __ldg(&adv[col + 1]);
            if (r0 < n)
                *(__half2*)&g_xph[(size_t)r0 * 128 + col] = __floats2half2_rn(acc[mt][j][0], acc[mt][j][1]);
            if (r1 < n)
                *(__half2*)&g_xph[(size_t)r1 * 128 + col] = __floats2half2_rn(acc[mt][j][2], acc[mt][j][3]);
            ps0 += acc[mt][j][0] * av0 + acc[mt][j][1] * av1;
            pd0 += acc[mt][j][0] * dv0 + acc[mt][j][1] * dv1;
            ps1 += acc[mt][j][2] * av0 + acc[mt][j][3] * av1;
            pd1 += acc[mt][j][2] * dv0 + acc[mt][j][3] * dv1;
        }
        atomicAdd(&sS[lr0], ps0); atomicAdd(&sD[lr0], pd0);
        atomicAdd(&sS[lr1], ps1); atomicAdd(&sD[lr1], pd1);
    }
    __syncthreads();
    if (tid < 128 && row0 + tid < n) {
        g_als[row0 + tid] = sS[tid];
        g_ald[row0 + tid] = sD[tid];
    }
}

// ================= fused GAT softmax-aggregate (warp per dst node) =================
// EPILOGUE: 0 = bias+relu -> g_h ; 1 = bias+relu -> atomic pool (layer 3)
template <int EPILOGUE>
__global__ __launch_bounds__(256) void k_gat_agg(const float* __restrict__ b,
                                                 const int* __restrict__ batch, int n) {
    int w = (blockIdx.x * blockDim.x + threadIdx.x) >> 5;
    int lane = threadIdx.x & 31;
    if (w >= n) return;
    int row = g_rowptr[w], end = g_rowptr[w + 1];
    int cnt = end - row;
    float ald_d = g_ald[w];
    float a_self = lrelu(g_als[w] + ald_d);
    const uint2* xpv = (const uint2*)g_xph;   // 4 halves per lane
    float4 acc;

    if (cnt <= 32) {
        int s_reg = 0;
        float a_reg = -1e30f;
        if (lane < cnt) {
            s_reg = g_csrc[row + lane];
            a_reg = lrelu(g_als[s_reg] + ald_d);
        }
        float m = fmaxf(a_reg, a_self);
#pragma unroll
        for (int o = 16; o > 0; o >>= 1)
            m = fmaxf(m, __shfl_xor_sync(FULLMASK, m, o));
        float p = (lane < cnt) ? __expf(a_reg - m) : 0.f;
        float den = p;
#pragma unroll
        for (int o = 16; o > 0; o >>= 1)
            den += __shfl_xor_sync(FULLMASK, den, o);
        float eself = __expf(a_self - m);
        float rden = 1.0f / (den + eself);
        p *= rden;

        float cself = eself * rden;
        float4 sv = h4_to_f4(xpv[(size_t)w * 32 + lane]);
        acc = make_float4(cself * sv.x, cself * sv.y, cself * sv.z, cself * sv.w);
        for (int j = 0; j < cnt; j++) {
            float coef = __shfl_sync(FULLMASK, p, j);
            int s = __shfl_sync(FULLMASK, s_reg, j);
            float4 v = h4_to_f4(xpv[(size_t)s * 32 + lane]);
            acc.x += coef * v.x; acc.y += coef * v.y;
            acc.z += coef * v.z; acc.w += coef * v.w;
        }
    } else {
        float m = a_self;
        for (int e = row + lane; e < end; e += 32)
            m = fmaxf(m, lrelu(__ldg(&g_als[g_csrc[e]]) + ald_d));
#pragma unroll
        for (int o = 16; o > 0; o >>= 1)
            m = fmaxf(m, __shfl_xor_sync(FULLMASK, m, o));
        float den = (lane == 0) ? __expf(a_self - m) : 0.f;
        for (int e = row + lane; e < end; e += 32)
            den += __expf(lrelu(__ldg(&g_als[g_csrc[e]]) + ald_d) - m);
#pragma unroll
        for (int o = 16; o > 0; o >>= 1)
            den += __shfl_xor_sync(FULLMASK, den, o);
        float rden = 1.0f / den;
        float cself = __expf(a_self - m) * rden;
        float4 sv = h4_to_f4(xpv[(size_t)w * 32 + lane]);
        acc = make_float4(cself * sv.x, cself * sv.y, cself * sv.z, cself * sv.w);
        for (int j = row; j < end; j++) {
            int s = g_csrc[j];
            float coef = __expf(lrelu(g_als[s] + ald_d) - m) * rden;
            float4 v = h4_to_f4(xpv[(size_t)s * 32 + lane]);
            acc.x += coef * v.x; acc.y += coef * v.y;
            acc.z += coef * v.z; acc.w += coef * v.w;
        }
    }

    float4 bb = ((const float4*)b)[lane];
    acc.x = fmaxf(acc.x + bb.x, 0.f);
    acc.y = fmaxf(acc.y + bb.y, 0.f);
    acc.z = fmaxf(acc.z + bb.z, 0.f);
    acc.w = fmaxf(acc.w + bb.w, 0.f);

    if (EPILOGUE == 0) {
        ((float4*)g_h)[(size_t)w * 32 + lane] = acc;
    } else {
        int g = batch[w];
        atomicAdd((float4*)&g_pool[g * 128 + lane * 4], acc);
        if (lane == 0) atomicAdd(&g_cnt[g], 1.0f);
    }
}

// ================= head =================
__global__ void k_final(const float* __restrict__ Wlin, const float* __restrict__ blin,
                        float* __restrict__ out) {
    int g = blockIdx.x;
    int j = threadIdx.x;
    __shared__ float s0[128], s1[128];
    float cnt = fmaxf(g_cnt[g], 1.0f);
    float p = g_pool[g * 128 + j] / cnt;
    s0[j] = p * Wlin[j * 2 + 0];
    s1[j] = p * Wlin[j * 2 + 1];
    __syncthreads();
#pragma unroll
    for (int st = 64; st > 0; st >>= 1) {
        if (j < st) { s0[j] += s0[j + st]; s1[j] += s1[j + st]; }
        __syncthreads();
    }
    if (j == 0) {
        out[g * 2 + 0] = 1.0f / (1.0f + __expf(-(s0[0] + blin[0])));
        out[g * 2 + 1] = 1.0f / (1.0f + __expf(-(s1[0] + blin[1])));
    }
}

// ================= host =================
extern "C" void kernel_launch(void* const* d_in, const int* in_sizes, int n_in,
                              void* d_out, int out_size) {
    const float* x     = (const float*)d_in[0];
    const int*   ei    = (const int*)d_in[1];
    const int*   batch = (const int*)d_in[2];
    const float* Wl[3] = { (const float*)d_in[3], (const float*)d_in[7],  (const float*)d_in[11] };
    const float* As[3] = { (const float*)d_in[4], (const float*)d_in[8],  (const float*)d_in[12] };
    const float* Ad[3] = { (const float*)d_in[5], (const float*)d_in[9],  (const float*)d_in[13] };
    const float* Bs[3] = { (const float*)d_in[6], (const float*)d_in[10], (const float*)d_in[14] };
    const float* Wlin  = (const float*)d_in[15];
    const float* blin  = (const float*)d_in[16];
    float* out = (float*)d_out;

    int n = in_sizes[0];
    int E = in_sizes[1] / 2;
    if (n > NMAX) n = NMAX;
    if (E > EMAX) E = EMAX;

    const int TB = 256;
    const int n32 = n * 32;
    dim3 gN32((n32 + TB - 1) / TB);
    dim3 gE((E + TB - 1) / TB);
    dim3 gNW(((size_t)n * 32 + TB - 1) / TB);
    dim3 gG((n + 127) / 128);
    int nBlk = (n + 1023) / 1024;

    static bool attr_done = false;
    if (!attr_done) {
        cudaFuncSetAttribute(k_gemm_tc, cudaFuncAttributeMaxDynamicSharedMemorySize, GEMM_SMEM);
        attr_done = true;
    }

    void *p_deg, *p_pool, *p_cnt;
    cudaGetSymbolAddress(&p_deg, g_deg);
    cudaGetSymbolAddress(&p_pool, g_pool);
    cudaGetSymbolAddress(&p_cnt, g_cnt);

    // CSR build
    cudaMemsetAsync(p_deg, 0, (size_t)n * sizeof(int));
    k_hist<<<gE, TB>>>(ei, E);
    k_scan_blk<<<nBlk, 1024>>>(n);
    k_scan_top<<<1, 64>>>(nBlk);
    k_scan_add<<<nBlk, 1024>>>(n);
    k_scatter<<<gE, TB>>>(ei, E);

    // zero pool accumulators (consumed by layer-3 fused agg+pool)
    cudaMemsetAsync(p_pool, 0, (size_t)NG * HID * sizeof(float));
    cudaMemsetAsync(p_cnt, 0, (size_t)NG * sizeof(float));

    // layer 1
    k_l1c<<<1, 128>>>(Wl[0], As[0], Ad[0]);
    k_l1<<<gN32, TB>>>(x, Wl[0], n32);
    k_gat_agg<0><<<gNW, TB>>>(Bs[0], batch, n);
    // layer 2
    k_gemm_tc<<<gG, TB, GEMM_SMEM>>>(Wl[1], As[1], Ad[1], n);
    k_gat_agg<0><<<gNW, TB>>>(Bs[1], batch, n);
    // layer 3 (fused pool)
    k_gemm_tc<<<gG, TB, GEMM_SMEM>>>(Wl[2], As[2], Ad[2], n);
    k_gat_agg<1><<<gNW, TB>>>(Bs[2], batch, n);

    k_final<<<NG, 128>>>(Wlin, blin, out);
}

// round 7
// speedup vs baseline: 2.3972x; 1.0080x over previous
#include <cuda_runtime.h>
#include <cuda_fp16.h>
#include <math.h>
#include <stdint.h>

#define NMAX 50000
#define EMAX 600000
#define HID  128
#define NG   64
#define FULLMASK 0xffffffffu

#define PADW 136
#define PADA 36
#define GEMM_SMEM ((128 * PADW + 128 * PADA) * 4)

// ---------------- device scratch ----------------
__device__ __align__(16) float  g_h [(size_t)NMAX * HID];   // fp32 GEMM input
__device__ __align__(16) __half g_xph[(size_t)NMAX * HID];  // fp16 gather payload
__device__ float g_als[NMAX];
__device__ float g_ald[NMAX];
__device__ __align__(16) float g_pool[NG * HID + NG];       // pool + cnt (single memset)
__device__ float g_c[2];
__device__ int   g_deg[NMAX];
__device__ int   g_rowptr[NMAX + 1];
__device__ int   g_wptr[NMAX];
__device__ int   g_csrc[EMAX];
__device__ int   g_bsum[64];
__device__ int   g_total;

__device__ __forceinline__ float lrelu(float a) { return (a > 0.f) ? a : 0.2f * a; }

__device__ __forceinline__ float to_tf32(float x) {
    float r;
    asm("cvt.rna.tf32.f32 %0, %1;" : "=f"(r) : "f"(x));
    return r;
}

__device__ __forceinline__ void mma_tf32(float c[4], const uint32_t a[4],
                                         uint32_t b0, uint32_t b1) {
    asm volatile(
        "mma.sync.aligned.m16n8k8.row.col.f32.tf32.tf32.f32 "
        "{%0,%1,%2,%3}, {%4,%5,%6,%7}, {%8,%9}, {%0,%1,%2,%3};"
        : "+f"(c[0]), "+f"(c[1]), "+f"(c[2]), "+f"(c[3])
        : "r"(a[0]), "r"(a[1]), "r"(a[2]), "r"(a[3]), "r"(b0), "r"(b1));
}

__device__ __forceinline__ float4 h4_to_f4(uint2 u) {
    float2 a = __half22float2(*(__half2*)&u.x);
    float2 b = __half22float2(*(__half2*)&u.y);
    return make_float4(a.x, a.y, b.x, b.y);
}

// ================= CSR build =================
__global__ void k_hist(const int* __restrict__ ei, int E) {
    int e = blockIdx.x * blockDim.x + threadIdx.x;
    if (e < E) atomicAdd(&g_deg[ei[E + e]], 1);
}

__global__ void k_scan_blk(int n) {
    __shared__ int warp_sums[32];
    int tid = threadIdx.x, lane = tid & 31, wid = tid >> 5;
    int i = blockIdx.x * 1024 + tid;
    int v = (i < n) ? g_deg[i] : 0;
    int x = v;
#pragma unroll
    for (int o = 1; o < 32; o <<= 1) {
        int y = __shfl_up_sync(FULLMASK, x, o);
        if (lane >= o) x += y;
    }
    if (lane == 31) warp_sums[wid] = x;
    __syncthreads();
    if (wid == 0) {
        int w = warp_sums[lane];
#pragma unroll
        for (int o = 1; o < 32; o <<= 1) {
            int y = __shfl_up_sync(FULLMASK, w, o);
            if (lane >= o) w += y;
        }
        warp_sums[lane] = w;
    }
    __syncthreads();
    int excl = (wid ? warp_sums[wid - 1] : 0) + x - v;
    if (i < n) g_rowptr[i] = excl;
    if (tid == 1023) g_bsum[blockIdx.x] = warp_sums[31];
}

__global__ void k_scan_top(int nb) {
    __shared__ int s[65];
    int tid = threadIdx.x;  // 64
    s[tid] = (tid < nb) ? g_bsum[tid] : 0;
    __syncthreads();
    if (tid == 0) {
        int run = 0;
        for (int i = 0; i < 64; i++) { int t = s[i]; s[i] = run; run += t; }
        s[64] = run;
        g_total = run;
    }
    __syncthreads();
    if (tid < nb) g_bsum[tid] = s[tid];
}

__global__ void k_scan_add(int n) {
    int i = blockIdx.x * 1024 + threadIdx.x;
    if (i < n) {
        int r = g_rowptr[i] + g_bsum[blockIdx.x];
        g_rowptr[i] = r;
        g_wptr[i] = r;
    }
    if (i == 0) g_rowptr[n] = g_total;
}

__global__ void k_scatter(const int* __restrict__ ei, int E) {
    int e = blockIdx.x * blockDim.x + threadIdx.x;
    if (e >= E) return;
    int d = ei[E + e];
    int pos = atomicAdd(&g_wptr[d], 1);
    g_csrc[pos] = ei[e];
}

// ================= layer 1 =================
__global__ void k_l1c(const float* __restrict__ W1, const float* __restrict__ as1,
                      const float* __restrict__ ad1) {
    __shared__ float s0[128], s1[128];
    int j = threadIdx.x;
    float w = W1[j];
    s0[j] = w * as1[j];
    s1[j] = w * ad1[j];
    __syncthreads();
#pragma unroll
    for (int st = 64; st > 0; st >>= 1) {
        if (j < st) { s0[j] += s0[j + st]; s1[j] += s1[j + st]; }
        __syncthreads();
    }
    if (j == 0) { g_c[0] = s0[0]; g_c[1] = s1[0]; }
}
__global__ void k_l1(const float* __restrict__ x, const float* __restrict__ W1, int n32) {
    int i = blockIdx.x * blockDim.x + threadIdx.x;
    if (i >= n32) return;
    int node = i >> 5;
    float xv = x[node];
    float4 w = ((const float4*)W1)[i & 31];
    uint2 st;
    *(__half2*)&st.x = __floats2half2_rn(xv * w.x, xv * w.y);
    *(__half2*)&st.y = __floats2half2_rn(xv * w.z, xv * w.w);
    ((uint2*)g_xph)[i] = st;
    if ((i & 31) == 0) {
        g_als[node] = xv * g_c[0];
        g_ald[node] = xv * g_c[1];
    }
}

// ================= tensor-core GEMM (TF32 mma) + fused attn scalars =================
__global__ __launch_bounds__(256, 2) void k_gemm_tc(const float* __restrict__ W,
                                                    const float* __restrict__ asv,
                                                    const float* __restrict__ adv, int n) {
    extern __shared__ float smem[];
    float* sW = smem;
    float* sA = smem + 128 * PADW;
    __shared__ float sS[128], sD[128];

    const int tid = threadIdx.x;
    const int row0 = blockIdx.x * 128;
    const int wid = tid >> 5, lane = tid & 31;
    const int wr = wid & 3;
    const int wc = wid >> 2;
    const int gid = lane >> 2, tig = lane & 3;

    if (tid < 128) { sS[tid] = 0.f; sD[tid] = 0.f; }

    for (int i = tid; i < 4096; i += 256) {
        int k = i >> 5;
        int c = (i & 31) * 4;
        float4 v = *(const float4*)&W[k * 128 + c];
        sW[k * PADW + c + 0] = to_tf32(v.x);
        sW[k * PADW + c + 1] = to_tf32(v.y);
        sW[k * PADW + c + 2] = to_tf32(v.z);
        sW[k * PADW + c + 3] = to_tf32(v.w);
    }

    float acc[2][8][4];
#pragma unroll
    for (int mt = 0; mt < 2; mt++)
#pragma unroll
        for (int j = 0; j < 8; j++)
#pragma unroll
            for (int q = 0; q < 4; q++) acc[mt][j][q] = 0.f;

    for (int kc = 0; kc < 4; kc++) {
        __syncthreads();
        for (int i = tid; i < 1024; i += 256) {
            int r = i >> 3;
            int c = (i & 7) * 4;
            float4 v = make_float4(0.f, 0.f, 0.f, 0.f);
            if (row0 + r < n)
                v = *(const float4*)&g_h[(size_t)(row0 + r) * 128 + kc * 32 + c];
            sA[r * PADA + c + 0] = to_tf32(v.x);
            sA[r * PADA + c + 1] = to_tf32(v.y);
            sA[r * PADA + c + 2] = to_tf32(v.z);
            sA[r * PADA + c + 3] = to_tf32(v.w);
        }
        __syncthreads();

#pragma unroll
        for (int ks = 0; ks < 4; ks++) {
            int k0 = ks * 8;
            uint32_t a[2][4];
#pragma unroll
            for (int mt = 0; mt < 2; mt++) {
                int base = wr * 32 + mt * 16;
                a[mt][0] = __float_as_uint(sA[(base + gid)     * PADA + k0 + tig]);
                a[mt][1] = __float_as_uint(sA[(base + gid + 8) * PADA + k0 + tig]);
                a[mt][2] = __float_as_uint(sA[(base + gid)     * PADA + k0 + tig + 4]);
                a[mt][3] = __float_as_uint(sA[(base + gid + 8) * PADA + k0 + tig + 4]);
            }
#pragma unroll
            for (int j = 0; j < 8; j++) {
                int col = wc * 64 + j * 8 + gid;
                uint32_t b0 = __float_as_uint(sW[(kc * 32 + k0 + tig)     * PADW + col]);
                uint32_t b1 = __float_as_uint(sW[(kc * 32 + k0 + tig + 4) * PADW + col]);
                mma_tf32(acc[0][j], a[0], b0, b1);
                mma_tf32(acc[1][j], a[1], b0, b1);
            }
        }
    }
    __syncthreads();

#pragma unroll
    for (int mt = 0; mt < 2; mt++) {
        int lr0 = wr * 32 + mt * 16 + gid;
        int lr1 = lr0 + 8;
        int r0 = row0 + lr0, r1 = row0 + lr1;
        float ps0 = 0.f, pd0 = 0.f, ps1 = 0.f, pd1 = 0.f;
#pragma unroll
        for (int j = 0; j < 8; j++) {
            int col = wc * 64 + j * 8 + tig * 2;
            float av0 = __ldg(&asv[col]), av1 = __ldg(&asv[col + 1]);
            float dv0 = __ldg(&adv[col]), dv1 = __ldg(&adv[col + 1]);
            if (r0 < n)
                *(__half2*)&g_xph[(size_t)r0 * 128 + col] = __floats2half2_rn(acc[mt][j][0], acc[mt][j][1]);
            if (r1 < n)
                *(__half2*)&g_xph[(size_t)r1 * 128 + col] = __floats2half2_rn(acc[mt][j][2], acc[mt][j][3]);
            ps0 += acc[mt][j][0] * av0 + acc[mt][j][1] * av1;
            pd0 += acc[mt][j][0] * dv0 + acc[mt][j][1] * dv1;
            ps1 += acc[mt][j][2] * av0 + acc[mt][j][3] * av1;
            pd1 += acc[mt][j][2] * dv0 + acc[mt][j][3] * dv1;
        }
        atomicAdd(&sS[lr0], ps0); atomicAdd(&sD[lr0], pd0);
        atomicAdd(&sS[lr1], ps1); atomicAdd(&sD[lr1], pd1);
    }
    __syncthreads();
    if (tid < 128 && row0 + tid < n) {
        g_als[row0 + tid] = sS[tid];
        g_ald[row0 + tid] = sD[tid];
    }
}

// ================= fused GAT softmax-aggregate (warp per dst node, MLP-4) =================
template <int EPILOGUE>
__global__ __launch_bounds__(256) void k_gat_agg(const float* __restrict__ b,
                                                 const int* __restrict__ batch, int n) {
    int w = (blockIdx.x * blockDim.x + threadIdx.x) >> 5;
    int lane = threadIdx.x & 31;
    if (w >= n) return;
    int row = g_rowptr[w], end = g_rowptr[w + 1];
    int cnt = end - row;
    float ald_d = g_ald[w];
    float a_self = lrelu(g_als[w] + ald_d);
    const uint2* xpv = (const uint2*)g_xph;
    float4 acc;

    if (cnt <= 32) {
        int s_reg = 0;
        float a_reg = -1e30f;
        if (lane < cnt) {
            s_reg = g_csrc[row + lane];
            a_reg = lrelu(g_als[s_reg] + ald_d);
        }
        float m = fmaxf(a_reg, a_self);
#pragma unroll
        for (int o = 16; o > 0; o >>= 1)
            m = fmaxf(m, __shfl_xor_sync(FULLMASK, m, o));
        float p = (lane < cnt) ? __expf(a_reg - m) : 0.f;
        float den = p;
#pragma unroll
        for (int o = 16; o > 0; o >>= 1)
            den += __shfl_xor_sync(FULLMASK, den, o);
        float eself = __expf(a_self - m);
        float rden = 1.0f / (den + eself);
        p *= rden;

        float cself = eself * rden;
        float4 sv = h4_to_f4(xpv[(size_t)w * 32 + lane]);
        acc = make_float4(cself * sv.x, cself * sv.y, cself * sv.z, cself * sv.w);

        int j = 0;
        for (; j + 4 <= cnt; j += 4) {          // 4 loads in flight
            float c0 = __shfl_sync(FULLMASK, p, j + 0);
            float c1 = __shfl_sync(FULLMASK, p, j + 1);
            float c2 = __shfl_sync(FULLMASK, p, j + 2);
            float c3 = __shfl_sync(FULLMASK, p, j + 3);
            int s0 = __shfl_sync(FULLMASK, s_reg, j + 0);
            int s1 = __shfl_sync(FULLMASK, s_reg, j + 1);
            int s2 = __shfl_sync(FULLMASK, s_reg, j + 2);
            int s3 = __shfl_sync(FULLMASK, s_reg, j + 3);
            uint2 u0 = xpv[(size_t)s0 * 32 + lane];
            uint2 u1 = xpv[(size_t)s1 * 32 + lane];
            uint2 u2 = xpv[(size_t)s2 * 32 + lane];
            uint2 u3 = xpv[(size_t)s3 * 32 + lane];
            float4 v0 = h4_to_f4(u0), v1 = h4_to_f4(u1);
            float4 v2 = h4_to_f4(u2), v3 = h4_to_f4(u3);
            acc.x += c0 * v0.x + c1 * v1.x + c2 * v2.x + c3 * v3.x;
            acc.y += c0 * v0.y + c1 * v1.y + c2 * v2.y + c3 * v3.y;
            acc.z += c0 * v0.z + c1 * v1.z + c2 * v2.z + c3 * v3.z;
            acc.w += c0 * v0.w + c1 * v1.w + c2 * v2.w + c3 * v3.w;
        }
        for (; j < cnt; j++) {
            float coef = __shfl_sync(FULLMASK, p, j);
            int s = __shfl_sync(FULLMASK, s_reg, j);
            float4 v = h4_to_f4(xpv[(size_t)s * 32 + lane]);
            acc.x += coef * v.x; acc.y += coef * v.y;
            acc.z += coef * v.z; acc.w += coef * v.w;
        }
    } else {
        float m = a_self;
        for (int e = row + lane; e < end; e += 32)
            m = fmaxf(m, lrelu(__ldg(&g_als[g_csrc[e]]) + ald_d));
#pragma unroll
        for (int o = 16; o > 0; o >>= 1)
            m = fmaxf(m, __shfl_xor_sync(FULLMASK, m, o));
        float den = (lane == 0) ? __expf(a_self - m) : 0.f;
        for (int e = row + lane; e < end; e += 32)
            den += __expf(lrelu(__ldg(&g_als[g_csrc[e]]) + ald_d) - m);
#pragma unroll
        for (int o = 16; o > 0; o >>= 1)
            den += __shfl_xor_sync(FULLMASK, den, o);
        float rden = 1.0f / den;
        float cself = __expf(a_self - m) * rden;
        float4 sv = h4_to_f4(xpv[(size_t)w * 32 + lane]);
        acc = make_float4(cself * sv.x, cself * sv.y, cself * sv.z, cself * sv.w);
        int j = row;
        for (; j + 2 <= end; j += 2) {
            int s0 = g_csrc[j], s1 = g_csrc[j + 1];
            float c0 = __expf(lrelu(g_als[s0] + ald_d) - m) * rden;
            float c1 = __expf(lrelu(g_als[s1] + ald_d) - m) * rden;
            uint2 u0 = xpv[(size_t)s0 * 32 + lane];
            uint2 u1 = xpv[(size_t)s1 * 32 + lane];
            float4 v0 = h4_to_f4(u0), v1 = h4_to_f4(u1);
            acc.x += c0 * v0.x + c1 * v1.x;
            acc.y += c0 * v0.y + c1 * v1.y;
            acc.z += c0 * v0.z + c1 * v1.z;
            acc.w += c0 * v0.w + c1 * v1.w;
        }
        for (; j < end; j++) {
            int s = g_csrc[j];
            float coef = __expf(lrelu(g_als[s] + ald_d) - m) * rden;
            float4 v = h4_to_f4(xpv[(size_t)s * 32 + lane]);
            acc.x += coef * v.x; acc.y += coef * v.y;
            acc.z += coef * v.z; acc.w += coef * v.w;
        }
    }

    float4 bb = ((const float4*)b)[lane];
    acc.x = fmaxf(acc.x + bb.x, 0.f);
    acc.y = fmaxf(acc.y + bb.y, 0.f);
    acc.z = fmaxf(acc.z + bb.z, 0.f);
    acc.w = fmaxf(acc.w + bb.w, 0.f);

    if (EPILOGUE == 0) {
        ((float4*)g_h)[(size_t)w * 32 + lane] = acc;
    } else {
        int g = batch[w];
        atomicAdd((float4*)&g_pool[g * 128 + lane * 4], acc);
        if (lane == 0) atomicAdd(&g_pool[NG * HID + g], 1.0f);
    }
}

// ================= head =================
__global__ void k_final(const float* __restrict__ Wlin, const float* __restrict__ blin,
                        float* __restrict__ out) {
    int g = blockIdx.x;
    int j = threadIdx.x;
    __shared__ float s0[128], s1[128];
    float cnt = fmaxf(g_pool[NG * HID + g], 1.0f);
    float p = g_pool[g * 128 + j] / cnt;
    s0[j] = p * Wlin[j * 2 + 0];
    s1[j] = p * Wlin[j * 2 + 1];
    __syncthreads();
#pragma unroll
    for (int st = 64; st > 0; st >>= 1) {
        if (j < st) { s0[j] += s0[j + st]; s1[j] += s1[j + st]; }
        __syncthreads();
    }
    if (j == 0) {
        out[g * 2 + 0] = 1.0f / (1.0f + __expf(-(s0[0] + blin[0])));
        out[g * 2 + 1] = 1.0f / (1.0f + __expf(-(s1[0] + blin[1])));
    }
}

// ================= host =================
extern "C" void kernel_launch(void* const* d_in, const int* in_sizes, int n_in,
                              void* d_out, int out_size) {
    const float* x     = (const float*)d_in[0];
    const int*   ei    = (const int*)d_in[1];
    const int*   batch = (const int*)d_in[2];
    const float* Wl[3] = { (const float*)d_in[3], (const float*)d_in[7],  (const float*)d_in[11] };
    const float* As[3] = { (const float*)d_in[4], (const float*)d_in[8],  (const float*)d_in[12] };
    const float* Ad[3] = { (const float*)d_in[5], (const float*)d_in[9],  (const float*)d_in[13] };
    const float* Bs[3] = { (const float*)d_in[6], (const float*)d_in[10], (const float*)d_in[14] };
    const float* Wlin  = (const float*)d_in[15];
    const float* blin  = (const float*)d_in[16];
    float* out = (float*)d_out;

    int n = in_sizes[0];
    int E = in_sizes[1] / 2;
    if (n > NMAX) n = NMAX;
    if (E > EMAX) E = EMAX;

    const int TB = 256;
    const int n32 = n * 32;
    dim3 gN32((n32 + TB - 1) / TB);
    dim3 gE((E + TB - 1) / TB);
    dim3 gNW(((size_t)n * 32 + TB - 1) / TB);
    dim3 gG((n + 127) / 128);
    int nBlk = (n + 1023) / 1024;

    static cudaStream_t s2 = nullptr;
    static cudaEvent_t evFork = nullptr, evJoin = nullptr;
    if (!s2) {
        cudaStreamCreateWithFlags(&s2, cudaStreamNonBlocking);
        cudaEventCreateWithFlags(&evFork, cudaEventDisableTiming);
        cudaEventCreateWithFlags(&evJoin, cudaEventDisableTiming);
        cudaFuncSetAttribute(k_gemm_tc, cudaFuncAttributeMaxDynamicSharedMemorySize, GEMM_SMEM);
    }

    void *p_deg, *p_pool;
    cudaGetSymbolAddress(&p_deg, g_deg);
    cudaGetSymbolAddress(&p_pool, g_pool);

    // ---- fork: CSR build on s2, layer-1 transform on main stream ----
    cudaEventRecord(evFork, 0);
    cudaStreamWaitEvent(s2, evFork, 0);

    cudaMemsetAsync(p_deg, 0, (size_t)n * sizeof(int), s2);
    k_hist<<<gE, TB, 0, s2>>>(ei, E);
    k_scan_blk<<<nBlk, 1024, 0, s2>>>(n);
    k_scan_top<<<1, 64, 0, s2>>>(nBlk);
    k_scan_add<<<nBlk, 1024, 0, s2>>>(n);
    k_scatter<<<gE, TB, 0, s2>>>(ei, E);
    cudaEventRecord(evJoin, s2);

    cudaMemsetAsync(p_pool, 0, (size_t)(NG * HID + NG) * sizeof(float));
    k_l1c<<<1, 128>>>(Wl[0], As[0], Ad[0]);
    k_l1<<<gN32, TB>>>(x, Wl[0], n32);

    cudaStreamWaitEvent(0, evJoin, 0);   // join before first aggregation

    // layer 1
    k_gat_agg<0><<<gNW, TB>>>(Bs[0], batch, n);
    // layer 2
    k_gemm_tc<<<gG, TB, GEMM_SMEM>>>(Wl[1], As[1], Ad[1], n);
    k_gat_agg<0><<<gNW, TB>>>(Bs[1], batch, n);
    // layer 3 (fused pool)
    k_gemm_tc<<<gG, TB, GEMM_SMEM>>>(Wl[2], As[2], Ad[2], n);
    k_gat_agg<1><<<gNW, TB>>>(Bs[2], batch, n);

    k_final<<<NG, 128>>>(Wlin, blin, out);
}